// round 3
// baseline (speedup 1.0000x reference)
#include <cuda_runtime.h>
#include <math.h>

#define Bb 2
#define Tt 2048
#define Cc 768
#define Hh 12

typedef unsigned long long ull;

static const long long CTll  = (long long)Cc * Tt;
static const long long BTCll = (long long)Bb * Tt * Cc;

// ---------------- workspace ----------------
#define WS_TM 0LL
#define WS_XB 1572864LL
#define WS_H1 20447232LL
#define WS_RIN 21233664LL
#define WS_KL 40108032LL
#define WS_AS 43253760LL
#define WS_GT 46399488LL
#define WS_Y  49545216LL
#define WS_YG 52690944LL
__device__ float g_ws[55836672];

// ---------------- f32x2 helpers ----------------
__device__ __forceinline__ void fma2(ull &d, ull a, ull b) {
    asm("fma.rn.f32x2 %0, %1, %2, %0;" : "+l"(d) : "l"(a), "l"(b));
}
__device__ __forceinline__ ull mul2(ull a, ull b) {
    ull d; asm("mul.rn.f32x2 %0, %1, %2;" : "=l"(d) : "l"(a), "l"(b)); return d;
}
__device__ __forceinline__ ull pk2(float v) {
    ull r; unsigned u = __float_as_uint(v);
    asm("mov.b64 %0, {%1, %1};" : "=l"(r) : "r"(u));
    return r;
}
__device__ __forceinline__ float lo2(ull p) { return __uint_as_float((unsigned)p); }
__device__ __forceinline__ float hi2(ull p) { return __uint_as_float((unsigned)(p >> 32)); }

// ---------------- GEMM ----------------
enum { EPI_NONE = 0, EPI_TANH = 1, EPI_MIX = 2, EPI_DECAY = 3, EPI_SIG = 4 };

struct ZMap {
    long long a[12], b[12], o[12], x1[12], x2[12];
    int epi[12];
};

// tile: TILEM x 128, 256 threads, per-thread (TILEM/16) m  x 8 n
template<int TILEM>
__global__ __launch_bounds__(256) void gemm_k(
    const float* __restrict__ A, int sAM, int sAK,
    const float* __restrict__ Bm, int sBK, int sBN,
    float* __restrict__ O, int sOM, int sON,
    int N, int K,
    const float* __restrict__ aux1, const float* __restrict__ aux2,
    ZMap zm)
{
    constexpr int MR = TILEM / 16;   // 8 or 4 rows per thread
    constexpr int MP = MR / 2;       // f32x2 pairs per thread

    int z = blockIdx.z;
    A  += zm.a[z];
    Bm += zm.b[z];
    O  += zm.o[z];
    const float* p1 = aux1 ? aux1 + zm.x1[z] : (const float*)0;
    const float* x2 = aux2 ? aux2 + zm.x2[z] : (const float*)0;
    const int epi = zm.epi[z];

    __shared__ __align__(16) float As[2][16][TILEM + 4];
    __shared__ __align__(16) float Bs[2][16][132];

    const int tid = threadIdx.x;
    const int m0 = blockIdx.y * TILEM, n0 = blockIdx.x * 128;
    const int tn = tid & 15, tm = tid >> 4;

    // loader index precompute
    const int a_mr128 = tid >> 1, a_ko128 = (tid & 1) * 8;   // A row-major, TILEM=128
    const int a_mr64  = tid >> 2, a_ko64  = (tid & 3) * 4;   // A row-major, TILEM=64
    const int a_kr    = tid >> 4;                            // A col-major
    const int a_mo128 = (tid & 15) * 8, a_mo64 = (tid & 15) * 4;
    const int b_kr    = tid >> 4, b_no = (tid & 15) * 8;     // B n-contig
    const int b_nr    = tid >> 1, b_ko = (tid & 1) * 8;      // B k-contig

    float4 ra0, ra1, rb0, rb1;

    ull acc[MP][8];
#pragma unroll
    for (int i = 0; i < MP; i++)
#pragma unroll
        for (int j = 0; j < 8; j++) acc[i][j] = 0ull;

#define LOAD_T(kt) do { \
    if (sAK == 1) { \
        if (TILEM == 128) { \
            const float* p_ = A + (long long)(m0 + a_mr128) * sAM + (kt) * 16 + a_ko128; \
            ra0 = *(const float4*)p_; ra1 = *(const float4*)(p_ + 4); \
        } else { \
            ra0 = *(const float4*)(A + (long long)(m0 + a_mr64) * sAM + (kt) * 16 + a_ko64); \
        } \
    } else { \
        const float* p_ = A + (long long)((kt) * 16 + a_kr) * sAK + m0; \
        if (TILEM == 128) { ra0 = *(const float4*)(p_ + a_mo128); ra1 = *(const float4*)(p_ + a_mo128 + 4); } \
        else             { ra0 = *(const float4*)(p_ + a_mo64); } \
    } \
    if (sBN == 1) { \
        const float* p_ = Bm + (long long)((kt) * 16 + b_kr) * sBK + n0 + b_no; \
        rb0 = *(const float4*)p_; rb1 = *(const float4*)(p_ + 4); \
    } else { \
        const float* p_ = Bm + (long long)(n0 + b_nr) * sBN + (kt) * 16 + b_ko; \
        rb0 = *(const float4*)p_; rb1 = *(const float4*)(p_ + 4); \
    } \
} while (0)

#define STORE_T(bf) do { \
    if (sAK == 1) { \
        if (TILEM == 128) { \
            As[bf][a_ko128+0][a_mr128] = ra0.x; As[bf][a_ko128+1][a_mr128] = ra0.y; \
            As[bf][a_ko128+2][a_mr128] = ra0.z; As[bf][a_ko128+3][a_mr128] = ra0.w; \
            As[bf][a_ko128+4][a_mr128] = ra1.x; As[bf][a_ko128+5][a_mr128] = ra1.y; \
            As[bf][a_ko128+6][a_mr128] = ra1.z; As[bf][a_ko128+7][a_mr128] = ra1.w; \
        } else { \
            As[bf][a_ko64+0][a_mr64] = ra0.x; As[bf][a_ko64+1][a_mr64] = ra0.y; \
            As[bf][a_ko64+2][a_mr64] = ra0.z; As[bf][a_ko64+3][a_mr64] = ra0.w; \
        } \
    } else { \
        if (TILEM == 128) { *(float4*)&As[bf][a_kr][a_mo128] = ra0; *(float4*)&As[bf][a_kr][a_mo128+4] = ra1; } \
        else              { *(float4*)&As[bf][a_kr][a_mo64] = ra0; } \
    } \
    if (sBN == 1) { \
        *(float4*)&Bs[bf][b_kr][b_no] = rb0; *(float4*)&Bs[bf][b_kr][b_no+4] = rb1; \
    } else { \
        Bs[bf][b_ko+0][b_nr] = rb0.x; Bs[bf][b_ko+1][b_nr] = rb0.y; \
        Bs[bf][b_ko+2][b_nr] = rb0.z; Bs[bf][b_ko+3][b_nr] = rb0.w; \
        Bs[bf][b_ko+4][b_nr] = rb1.x; Bs[bf][b_ko+5][b_nr] = rb1.y; \
        Bs[bf][b_ko+6][b_nr] = rb1.z; Bs[bf][b_ko+7][b_nr] = rb1.w; \
    } \
} while (0)

    const int nk = K >> 4;
    LOAD_T(0);
    STORE_T(0);
    __syncthreads();

    for (int kt = 0; kt < nk; kt++) {
        int buf = kt & 1;
        if (kt + 1 < nk) LOAD_T(kt + 1);
#pragma unroll 4
        for (int k = 0; k < 16; k++) {
            ulonglong2 a01 = *(const ulonglong2*)&As[buf][k][tm * MR];
            ulonglong2 a23;
            if (TILEM == 128) a23 = *(const ulonglong2*)&As[buf][k][tm * MR + 4];
            float4 b0 = *(const float4*)&Bs[buf][k][tn * 8];
            float4 b1 = *(const float4*)&Bs[buf][k][tn * 8 + 4];
            ull pb[8];
            pb[0] = pk2(b0.x); pb[1] = pk2(b0.y); pb[2] = pk2(b0.z); pb[3] = pk2(b0.w);
            pb[4] = pk2(b1.x); pb[5] = pk2(b1.y); pb[6] = pk2(b1.z); pb[7] = pk2(b1.w);
#pragma unroll
            for (int j = 0; j < 8; j++) {
                fma2(acc[0][j], a01.x, pb[j]);
                fma2(acc[1][j], a01.y, pb[j]);
                if (TILEM == 128) {
                    fma2(acc[2][j], a23.x, pb[j]);
                    fma2(acc[3][j], a23.y, pb[j]);
                }
            }
        }
        if (kt + 1 < nk) STORE_T(buf ^ 1);
        __syncthreads();
    }

    float vout[MR][8];
#pragma unroll
    for (int mp = 0; mp < MP; mp++)
#pragma unroll
        for (int j = 0; j < 8; j++) {
            vout[2 * mp][j]     = lo2(acc[mp][j]);
            vout[2 * mp + 1][j] = hi2(acc[mp][j]);
        }

#pragma unroll
    for (int r = 0; r < MR; r++) {
        int m = m0 + tm * MR + r;
#pragma unroll
        for (int j = 0; j < 8; j++) {
            int n = n0 + tn * 8 + j;
            float v = vout[r][j];
            if (epi == EPI_TANH) {
                v = tanhf(v);
            } else if (epi == EPI_MIX) {
                v = x2[(long long)m * N + n] * (1.f + p1[m] + v);
            } else if (epi == EPI_DECAY) {
                float u = -(p1[m] + v);
                float sp = fmaxf(u, 0.f) + log1pf(expf(-fabsf(u)));
                v = expf(-expf(-sp - 0.5f));
            } else if (epi == EPI_SIG) {
                v = 1.f / (1.f + expf(-(p1[m] + v)));
            }
            vout[r][j] = v;
        }
    }

    if (sON == 1) {
#pragma unroll
        for (int r = 0; r < MR; r++) {
            long long mb = (long long)(m0 + tm * MR + r) * sOM + n0 + tn * 8;
            *(float4*)(O + mb)     = make_float4(vout[r][0], vout[r][1], vout[r][2], vout[r][3]);
            *(float4*)(O + mb + 4) = make_float4(vout[r][4], vout[r][5], vout[r][6], vout[r][7]);
        }
    } else {
#pragma unroll
        for (int j = 0; j < 8; j++) {
            long long nb = (long long)(n0 + tn * 8 + j) * sON + m0 + tm * MR;
            *(float4*)(O + nb) = make_float4(vout[0][j], vout[1][j], vout[2][j], vout[3][j]);
            if (TILEM == 128)
                *(float4*)(O + nb + 4) = make_float4(vout[4][j], vout[5][j], vout[6][j], vout[7][j]);
        }
    }
#undef LOAD_T
#undef STORE_T
}

// ---------------- E1 ----------------
__global__ __launch_bounds__(256) void e1_k(
    const float* __restrict__ kc, const float* __restrict__ kl,
    const float* __restrict__ asig, float* __restrict__ am, float* __restrict__ bm)
{
    int gw = (int)((blockIdx.x * blockDim.x + threadIdx.x) >> 5);
    int lane = threadIdx.x & 31;
    long long base = (long long)gw * 64;
    float k1 = kc[base + lane]      + kl[base + lane];
    float k2 = kc[base + lane + 32] + kl[base + lane + 32];
    float ss = k1 * k1 + k2 * k2;
#pragma unroll
    for (int o = 16; o; o >>= 1) ss += __shfl_xor_sync(0xffffffffu, ss, o);
    float inv = 1.f / fmaxf(sqrtf(ss), 1e-12f);
    float n1 = k1 * inv, n2 = k2 * inv;
    am[base + lane]      = -n1;
    am[base + lane + 32] = -n2;
    bm[base + lane]      = n1 * asig[base + lane];
    bm[base + lane + 32] = n2 * asig[base + lane + 32];
}

// ---------------- WKV7 ----------------
#define RS 4
__global__ __launch_bounds__(64) void wkv7_k(const float* __restrict__ rin, float* __restrict__ y)
{
    int blk = blockIdx.x;
    int rs = blk & 3;
    int bh = blk >> 2;
    int b = bh / Hh, h = bh % Hh;
    long long base = (long long)b * Tt * Cc + (long long)h * 64;

    int tid = threadIdx.x;
    int lr = tid >> 2, jc = tid & 3;
    int i = rs * 16 + lr;
    int jb = jc << 4;

    __shared__ __align__(16) float sh[2][384];

#pragma unroll
    for (int q = 0; q < 6; q++)
        sh[0][q * 64 + tid] = rin[(long long)q * BTCll + base + tid];
    __syncthreads();

    ull S2[8];
#pragma unroll
    for (int u = 0; u < 8; u++) S2[u] = 0ull;
    float sa = 0.f;

    for (int t = 0; t < Tt; t++) {
        int cur = t & 1, nxt = cur ^ 1;
        float pf[6];
        if (t + 1 < Tt) {
            long long off = base + (long long)(t + 1) * Cc;
#pragma unroll
            for (int q = 0; q < 6; q++)
                pf[q] = rin[(long long)q * BTCll + off + tid];
        } else {
#pragma unroll
            for (int q = 0; q < 6; q++) pf[q] = 0.f;
        }

        const float* sb = &sh[cur][0];
        float vi = sb[3 * 64 + i];
        ull vi2 = pk2(vi), sa2 = pk2(sa);

        const ulonglong2* wp = (const ulonglong2*)(sb + 1 * 64 + jb);
        const ulonglong2* kp = (const ulonglong2*)(sb + 2 * 64 + jb);
        const ulonglong2* bp = (const ulonglong2*)(sb + 5 * 64 + jb);
        const ulonglong2* rp = (const ulonglong2*)(sb + 0 * 64 + jb);

#pragma unroll
        for (int q = 0; q < 4; q++) {
            ulonglong2 wv = wp[q], kv = kp[q], bv = bp[q];
            ull d0 = mul2(vi2, kv.x);
            fma2(d0, sa2, bv.x);
            fma2(d0, S2[2 * q], wv.x);
            S2[2 * q] = d0;
            ull d1 = mul2(vi2, kv.y);
            fma2(d1, sa2, bv.y);
            fma2(d1, S2[2 * q + 1], wv.y);
            S2[2 * q + 1] = d1;
        }

        ull ya = 0ull, yb = 0ull;
#pragma unroll
        for (int q = 0; q < 4; q++) {
            ulonglong2 rv = rp[q];
            fma2(ya, S2[2 * q], rv.x);
            fma2(yb, S2[2 * q + 1], rv.y);
        }

        float* sn = &sh[nxt][0];
#pragma unroll
        for (int q = 0; q < 6; q++) sn[q * 64 + tid] = pf[q];
        __syncthreads();

        const ulonglong2* ap = (const ulonglong2*)(&sh[nxt][4 * 64 + jb]);
        ull za = 0ull, zb = 0ull;
#pragma unroll
        for (int q = 0; q < 4; q++) {
            ulonglong2 av = ap[q];
            fma2(za, S2[2 * q], av.x);
            fma2(zb, S2[2 * q + 1], av.y);
        }

        float yv = (lo2(ya) + hi2(ya)) + (lo2(yb) + hi2(yb));
        float sv = (lo2(za) + hi2(za)) + (lo2(zb) + hi2(zb));
        yv += __shfl_xor_sync(0xffffffffu, yv, 1);
        sv += __shfl_xor_sync(0xffffffffu, sv, 1);
        yv += __shfl_xor_sync(0xffffffffu, yv, 2);
        sv += __shfl_xor_sync(0xffffffffu, sv, 2);
        sa = sv;
        if (jc == 0)
            y[base + (long long)t * Cc + i] = yv;
    }
}

// ---------------- E2 ----------------
__global__ __launch_bounds__(768) void e2_k(
    const float* __restrict__ y,
    const float* __restrict__ rr, const float* __restrict__ kk, const float* __restrict__ vv,
    const float* __restrict__ gg, const float* __restrict__ faaaa,
    const float* __restrict__ lnw, float* __restrict__ yg)
{
    long long base = (long long)blockIdx.x * Cc;
    int c = threadIdx.x;
    int w = c >> 5, h = c >> 6, j = c & 63, lane = c & 31;
    float yv = y[base + c];
    float rv = rr[base + c], kv = kk[base + c], vV = vv[base + c];
    float s1 = yv * yv;
    float s2 = rv * kv * faaaa[h * 64 + j];
#pragma unroll
    for (int o = 16; o; o >>= 1) {
        s1 += __shfl_xor_sync(0xffffffffu, s1, o);
        s2 += __shfl_xor_sync(0xffffffffu, s2, o);
    }
    __shared__ float sh1[24], sh2[24];
    if (lane == 0) { sh1[w] = s1; sh2[w] = s2; }
    __syncthreads();
    float tot = 0.f;
#pragma unroll
    for (int q = 0; q < 24; q++) tot += sh1[q];
    float scale = rsqrtf(tot * (1.f / 768.f) + 1e-5f);
    float rk = sh2[h * 2] + sh2[h * 2 + 1];
    float yo = yv * scale * lnw[c] + rk * vV;
    yg[base + c] = yo * gg[base + c];
}

// ---------------- launch ----------------
static inline long long pdiff(const void* p, const void* base) {
    return (long long)((const float*)p - (const float*)base);
}

extern "C" void kernel_launch(void* const* d_in, const int* in_sizes, int n_in,
                              void* d_out, int out_size)
{
    (void)in_sizes; (void)n_in; (void)out_size;
    const float* x       = (const float*)d_in[0];
    const float* tmaa_r  = (const float*)d_in[2];
    const float* tmaa_w  = (const float*)d_in[3];
    const float* tmaa_k  = (const float*)d_in[4];
    const float* tmaa_v  = (const float*)d_in[5];
    const float* tmaa_a  = (const float*)d_in[6];
    const float* tmaa_g  = (const float*)d_in[7];
    const float* tdecay  = (const float*)d_in[8];
    const float* faaaa   = (const float*)d_in[9];
    const float* taaaaa  = (const float*)d_in[10];
    const float* maa_w1  = (const float*)d_in[11];
    const float* maa_w2  = (const float*)d_in[12];
    const float* dec_w1  = (const float*)d_in[13];
    const float* dec_w2  = (const float*)d_in[14];
    const float* aaa_w1  = (const float*)d_in[15];
    const float* aaa_w2  = (const float*)d_in[16];
    const float* kkk_w1  = (const float*)d_in[17];
    const float* kkk_w2  = (const float*)d_in[18];
    const float* gate_w1 = (const float*)d_in[19];
    const float* gate_w2 = (const float*)d_in[20];
    const float* w_key   = (const float*)d_in[21];
    const float* w_val   = (const float*)d_in[22];
    const float* w_rec   = (const float*)d_in[23];
    const float* w_out   = (const float*)d_in[24];
    const float* lnw     = (const float*)d_in[25];
    float* out = (float*)d_out;

    float* ws = 0;
    cudaGetSymbolAddress((void**)&ws, g_ws);

    float* TM  = ws + WS_TM;
    float* XB  = ws + WS_XB;
    float* H1  = ws + WS_H1;
    float* RIN = ws + WS_RIN;
    float* KL  = ws + WS_KL;
    float* AS  = ws + WS_AS;
    float* GT  = ws + WS_GT;
    float* Y   = ws + WS_Y;
    float* YG  = ws + WS_YG;

    // 1) TM = tanh(maa_w1 @ x): M=384, K=768
    {
        ZMap zm = {};
        for (int b = 0; b < 2; b++) {
            zm.b[b] = (long long)b * CTll;
            zm.o[b] = (long long)b * 384 * Tt;
            zm.epi[b] = EPI_TANH;
        }
        gemm_k<128><<<dim3(16, 3, 2), 256>>>(maa_w1, 768, 1, x, Tt, 1, TM, Tt, 1,
                                             2048, 768, 0, 0, zm);
    }

    // 2) MIX: z = n*2+b, M=768, K=64, A col-major
    {
        ZMap zm = {};
        const float* tmaas[6] = {tmaa_r, tmaa_w, tmaa_k, tmaa_v, tmaa_a, tmaa_g};
        for (int n = 0; n < 6; n++)
            for (int b = 0; b < 2; b++) {
                int z = n * 2 + b;
                zm.a[z]  = (long long)n * 64 * Cc;
                zm.b[z]  = (long long)b * 384 * Tt + (long long)n * 64 * Tt;
                zm.o[z]  = (long long)n * BTCll + (long long)b * CTll;
                zm.x1[z] = pdiff(tmaas[n], tmaa_r);
                zm.x2[z] = (long long)b * CTll;
                zm.epi[z] = EPI_MIX;
            }
        gemm_k<128><<<dim3(16, 6, 12), 256>>>(maa_w2, 1, Cc, TM, Tt, 1, XB, Tt, 1,
                                              2048, 64, tmaa_r, x, zm);
    }

    // 3) convs (r,k,v): z = q*4+g*2+b, M=384, K=384
    {
        ZMap zm = {};
        long long qd[3] = {0, pdiff(w_key, w_rec), pdiff(w_val, w_rec)};
        const int xbi[3] = {0, 2, 3};
        const int rio[3] = {0, 2, 3};
        for (int q = 0; q < 3; q++)
            for (int g = 0; g < 2; g++)
                for (int b = 0; b < 2; b++) {
                    int z = q * 4 + g * 2 + b;
                    zm.a[z] = qd[q] + (long long)g * 384 * 384;
                    zm.b[z] = (long long)xbi[q] * BTCll + (long long)b * CTll + (long long)g * 384 * Tt;
                    zm.o[z] = (long long)rio[q] * BTCll + (long long)b * Tt * Cc + g * 384;
                    zm.epi[z] = EPI_NONE;
                }
        gemm_k<128><<<dim3(16, 3, 12), 256>>>(w_rec, 384, 1, XB, Tt, 1, RIN, 1, Cc,
                                              2048, 384, 0, 0, zm);
    }

    // 4) lora stage1 (dec,kkk,aaa): M=64, K=768
    {
        ZMap zm = {};
        long long qd[3] = {0, pdiff(kkk_w1, dec_w1), pdiff(aaa_w1, dec_w1)};
        const int sl[3] = {1, 2, 4};
        for (int q = 0; q < 3; q++)
            for (int b = 0; b < 2; b++) {
                int z = q * 2 + b;
                zm.a[z] = qd[q];
                zm.b[z] = (long long)sl[q] * BTCll + (long long)b * CTll;
                zm.o[z] = (long long)q * (2LL * 64 * Tt) + (long long)b * 64 * Tt;
                zm.epi[z] = EPI_TANH;
            }
        gemm_k<64><<<dim3(16, 1, 6), 256>>>(dec_w1, 768, 1, XB, Tt, 1, H1, Tt, 1,
                                            2048, 768, 0, 0, zm);
    }

    // 5) gate stage1: M=192, K=768
    {
        ZMap zm = {};
        for (int b = 0; b < 2; b++) {
            zm.b[b] = 5LL * BTCll + (long long)b * CTll;
            zm.o[b] = (long long)b * 192 * Tt;
            zm.epi[b] = EPI_TANH;
        }
        gemm_k<64><<<dim3(16, 3, 2), 256>>>(gate_w1, 768, 1, XB, Tt, 1, TM, Tt, 1,
                                            2048, 768, 0, 0, zm);
    }

    // 6) lora stage2: M=768, K=64, per-z epilogue
    {
        ZMap zm = {};
        long long qd[3] = {0, pdiff(kkk_w2, dec_w2), pdiff(aaa_w2, dec_w2)};
        long long od[3] = {WS_RIN + BTCll, WS_KL, WS_AS};
        const int ep[3] = {EPI_DECAY, EPI_NONE, EPI_SIG};
        long long xd[3] = {0, 0, pdiff(taaaaa, tdecay)};
        for (int q = 0; q < 3; q++)
            for (int b = 0; b < 2; b++) {
                int z = q * 2 + b;
                zm.a[z]  = qd[q];
                zm.b[z]  = (long long)q * (2LL * 64 * Tt) + (long long)b * 64 * Tt;
                zm.o[z]  = od[q] + (long long)b * Tt * Cc;
                zm.x1[z] = xd[q];
                zm.epi[z] = ep[q];
            }
        gemm_k<128><<<dim3(16, 6, 6), 256>>>(dec_w2, 64, 1, H1, Tt, 1, ws, 1, Cc,
                                             2048, 64, tdecay, 0, zm);
    }

    // 7) gate stage2: M=768, K=192
    {
        ZMap zm = {};
        for (int b = 0; b < 2; b++) {
            zm.b[b] = (long long)b * 192 * Tt;
            zm.o[b] = (long long)b * Tt * Cc;
            zm.epi[b] = EPI_NONE;
        }
        gemm_k<128><<<dim3(16, 6, 2), 256>>>(gate_w2, 192, 1, TM, Tt, 1, GT, 1, Cc,
                                             2048, 192, 0, 0, zm);
    }

    // 8) E1
    e1_k<<<(Bb * Tt * Hh) / 8, 256>>>(RIN + 2 * BTCll, KL, AS,
                                      RIN + 4 * BTCll, RIN + 5 * BTCll);

    // 9) WKV7
    wkv7_k<<<Bb * Hh * RS, 64>>>(RIN, Y);

    // 10) E2
    e2_k<<<Bb * Tt, 768>>>(Y, RIN, RIN + 2 * BTCll, RIN + 3 * BTCll,
                           GT, faaaa, lnw, YG);

    // 11) output conv: M=384, K=384
    {
        ZMap zm = {};
        for (int g = 0; g < 2; g++)
            for (int b = 0; b < 2; b++) {
                int z = g * 2 + b;
                zm.a[z] = (long long)g * 384 * 384;
                zm.b[z] = (long long)b * Tt * Cc + g * 384;
                zm.o[z] = (long long)b * CTll + (long long)g * 384 * Tt;
                zm.epi[z] = EPI_NONE;
            }
        gemm_k<128><<<dim3(16, 3, 4), 256>>>(w_out, 384, 1, YG, 1, Cc, out, Tt, 1,
                                             2048, 384, 0, 0, zm);
    }
}

// round 4
// speedup vs baseline: 1.0569x; 1.0569x over previous
#include <cuda_runtime.h>
#include <math.h>

#define Bb 2
#define Tt 2048
#define Cc 768
#define Hh 12

typedef unsigned long long ull;

static const long long CTll  = (long long)Cc * Tt;
static const long long BTCll = (long long)Bb * Tt * Cc;

// ---------------- workspace ----------------
#define WS_TM 0LL
#define WS_XB 1572864LL
#define WS_H1 20447232LL
#define WS_RIN 21233664LL
#define WS_KL 40108032LL
#define WS_AS 43253760LL
#define WS_GT 46399488LL
#define WS_Y  49545216LL
#define WS_YG 52690944LL
__device__ float g_ws[55836672];

// ---------------- f32x2 helpers (WKV) ----------------
__device__ __forceinline__ void fma2(ull &d, ull a, ull b) {
    asm("fma.rn.f32x2 %0, %1, %2, %0;" : "+l"(d) : "l"(a), "l"(b));
}
__device__ __forceinline__ ull mul2(ull a, ull b) {
    ull d; asm("mul.rn.f32x2 %0, %1, %2;" : "=l"(d) : "l"(a), "l"(b)); return d;
}
__device__ __forceinline__ ull pk2(float v) {
    ull r; unsigned u = __float_as_uint(v);
    asm("mov.b64 %0, {%1, %1};" : "=l"(r) : "r"(u));
    return r;
}
__device__ __forceinline__ float lo2(ull p) { return __uint_as_float((unsigned)p); }
__device__ __forceinline__ float hi2(ull p) { return __uint_as_float((unsigned)(p >> 32)); }

// ---------------- tf32 helpers ----------------
__device__ __forceinline__ unsigned cvt_tf32(float x) {
    unsigned r; asm("cvt.rna.tf32.f32 %0, %1;" : "=r"(r) : "f"(x)); return r;
}
__device__ __forceinline__ void put_hl(float* hi, float* lo, float v) {
    float h = __uint_as_float(cvt_tf32(v));
    *hi = h;
    *lo = __uint_as_float(cvt_tf32(v - h));
}
__device__ __forceinline__ void mma8(float c[4], const float a[4], unsigned b0, unsigned b1) {
    asm volatile("mma.sync.aligned.m16n8k8.row.col.f32.tf32.tf32.f32 "
        "{%0,%1,%2,%3}, {%4,%5,%6,%7}, {%8,%9}, {%0,%1,%2,%3};"
        : "+f"(c[0]), "+f"(c[1]), "+f"(c[2]), "+f"(c[3])
        : "r"(__float_as_uint(a[0])), "r"(__float_as_uint(a[1])),
          "r"(__float_as_uint(a[2])), "r"(__float_as_uint(a[3])),
          "r"(b0), "r"(b1));
}

// ---------------- GEMM (tensor core, 3xTF32) ----------------
enum { EPI_NONE = 0, EPI_TANH = 1, EPI_MIX = 2, EPI_DECAY = 3, EPI_SIG = 4 };

struct ZMap {
    long long a[12], b[12], o[12], x1[12], x2[12];
    int epi[12];
};

__device__ __forceinline__ float apply_epi(float v, int epi, const float* p1,
                                           const float* x2, int m, int n, int N) {
    if (epi == EPI_TANH) {
        v = tanhf(v);
    } else if (epi == EPI_MIX) {
        v = x2[(long long)m * N + n] * (1.f + p1[m] + v);
    } else if (epi == EPI_DECAY) {
        float u = -(p1[m] + v);
        float sp = fmaxf(u, 0.f) + log1pf(expf(-fabsf(u)));
        v = expf(-expf(-sp - 0.5f));
    } else if (epi == EPI_SIG) {
        v = 1.f / (1.f + expf(-(p1[m] + v)));
    }
    return v;
}

// tile: TILEM x 64, 256 threads (8 warps), warp tile 32 x (TILEM==128 ? 32 : 16)
template<int TILEM>
__global__ __launch_bounds__(256) void gemm_k(
    const float* __restrict__ A, int sAM, int sAK,
    const float* __restrict__ Bm, int sBK, int sBN,
    float* __restrict__ O, int sOM, int sON,
    int N, int K,
    const float* __restrict__ aux1, const float* __restrict__ aux2,
    ZMap zm)
{
    constexpr int MT = 2;                       // m16 tiles per warp
    constexpr int NT = (TILEM == 128) ? 4 : 2;  // n8 tiles per warp
    constexpr int APAD = TILEM + 8;

    int z = blockIdx.z;
    A  += zm.a[z];
    Bm += zm.b[z];
    O  += zm.o[z];
    const float* p1 = aux1 ? aux1 + zm.x1[z] : (const float*)0;
    const float* x2 = aux2 ? aux2 + zm.x2[z] : (const float*)0;
    const int epi = zm.epi[z];

    __shared__ __align__(16) float As[2][2][8][APAD];  // [buf][hi/lo][k][m]
    __shared__ __align__(16) float Bs[2][2][8][72];    // [buf][hi/lo][k][n]

    const int tid = threadIdx.x;
    const int m0 = blockIdx.y * TILEM, n0 = blockIdx.x * 64;
    const int warp = tid >> 5, lane = tid & 31;
    const int qr = lane >> 2, qc = lane & 3;

    int wm0, wn0;
    if (TILEM == 128) { wm0 = (warp >> 1) * 32; wn0 = (warp & 1) * 32; }
    else              { wm0 = (warp >> 2) * 32; wn0 = (warp & 3) * 16; }

    // loader indices
    const int arm_m  = (TILEM == 128) ? (tid >> 1) : (tid >> 2);
    const int arm_ko = (TILEM == 128) ? ((tid & 1) * 4) : ((tid & 3) * 2);
    const int acm_k  = tid >> 5;
    const int acm_mo = (TILEM == 128) ? ((tid & 31) * 4) : ((tid & 31) * 2);
    const int bnc_k  = tid >> 5;
    const int bnc_no = (tid & 31) * 2;
    const int bkc_n  = tid >> 2;
    const int bkc_ko = (tid & 3) * 2;

    float va[4], vb[2];

#define LOAD_T(kt) do { \
    if (sAK == 1) { \
        const float* p_ = A + (long long)(m0 + arm_m) * sAM + (kt) * 8 + arm_ko; \
        if (TILEM == 128) { float4 t_ = *(const float4*)p_; va[0]=t_.x; va[1]=t_.y; va[2]=t_.z; va[3]=t_.w; } \
        else              { float2 t_ = *(const float2*)p_; va[0]=t_.x; va[1]=t_.y; } \
    } else { \
        const float* p_ = A + (long long)((kt) * 8 + acm_k) * sAK + m0 + acm_mo; \
        if (TILEM == 128) { float4 t_ = *(const float4*)p_; va[0]=t_.x; va[1]=t_.y; va[2]=t_.z; va[3]=t_.w; } \
        else              { float2 t_ = *(const float2*)p_; va[0]=t_.x; va[1]=t_.y; } \
    } \
    if (sBN == 1) { \
        const float* p_ = Bm + (long long)((kt) * 8 + bnc_k) * sBK + n0 + bnc_no; \
        float2 t_ = *(const float2*)p_; vb[0] = t_.x; vb[1] = t_.y; \
    } else { \
        const float* p_ = Bm + (long long)(n0 + bkc_n) * sBN + (kt) * 8 + bkc_ko; \
        float2 t_ = *(const float2*)p_; vb[0] = t_.x; vb[1] = t_.y; \
    } \
} while (0)

#define STORE_T(bf) do { \
    if (sAK == 1) { \
        if (TILEM == 128) { \
            for (int j_ = 0; j_ < 4; j_++) \
                put_hl(&As[bf][0][arm_ko + j_][arm_m], &As[bf][1][arm_ko + j_][arm_m], va[j_]); \
        } else { \
            for (int j_ = 0; j_ < 2; j_++) \
                put_hl(&As[bf][0][arm_ko + j_][arm_m], &As[bf][1][arm_ko + j_][arm_m], va[j_]); \
        } \
    } else { \
        if (TILEM == 128) { \
            for (int j_ = 0; j_ < 4; j_++) \
                put_hl(&As[bf][0][acm_k][acm_mo + j_], &As[bf][1][acm_k][acm_mo + j_], va[j_]); \
        } else { \
            for (int j_ = 0; j_ < 2; j_++) \
                put_hl(&As[bf][0][acm_k][acm_mo + j_], &As[bf][1][acm_k][acm_mo + j_], va[j_]); \
        } \
    } \
    if (sBN == 1) { \
        for (int j_ = 0; j_ < 2; j_++) \
            put_hl(&Bs[bf][0][bnc_k][bnc_no + j_], &Bs[bf][1][bnc_k][bnc_no + j_], vb[j_]); \
    } else { \
        for (int j_ = 0; j_ < 2; j_++) \
            put_hl(&Bs[bf][0][bkc_ko + j_][bkc_n], &Bs[bf][1][bkc_ko + j_][bkc_n], vb[j_]); \
    } \
} while (0)

    float c[MT][NT][4];
#pragma unroll
    for (int mt = 0; mt < MT; mt++)
#pragma unroll
        for (int nt = 0; nt < NT; nt++)
#pragma unroll
            for (int r = 0; r < 4; r++) c[mt][nt][r] = 0.f;

    const int nk = K >> 3;
    LOAD_T(0);
    STORE_T(0);
    __syncthreads();

    for (int kt = 0; kt < nk; kt++) {
        int buf = kt & 1;
        if (kt + 1 < nk) LOAD_T(kt + 1);

        float ah[MT][4], al[MT][4];
#pragma unroll
        for (int mt = 0; mt < MT; mt++) {
            int am = wm0 + mt * 16 + qr;
            ah[mt][0] = As[buf][0][qc][am];     ah[mt][1] = As[buf][0][qc][am + 8];
            ah[mt][2] = As[buf][0][qc + 4][am]; ah[mt][3] = As[buf][0][qc + 4][am + 8];
            al[mt][0] = As[buf][1][qc][am];     al[mt][1] = As[buf][1][qc][am + 8];
            al[mt][2] = As[buf][1][qc + 4][am]; al[mt][3] = As[buf][1][qc + 4][am + 8];
        }
#pragma unroll
        for (int nt = 0; nt < NT; nt++) {
            int bn = wn0 + nt * 8 + qr;
            unsigned bh0 = __float_as_uint(Bs[buf][0][qc][bn]);
            unsigned bh1 = __float_as_uint(Bs[buf][0][qc + 4][bn]);
            unsigned bl0 = __float_as_uint(Bs[buf][1][qc][bn]);
            unsigned bl1 = __float_as_uint(Bs[buf][1][qc + 4][bn]);
#pragma unroll
            for (int mt = 0; mt < MT; mt++) {
                mma8(c[mt][nt], ah[mt], bh0, bh1);
                mma8(c[mt][nt], al[mt], bh0, bh1);
                mma8(c[mt][nt], ah[mt], bl0, bl1);
            }
        }

        if (kt + 1 < nk) STORE_T(buf ^ 1);
        __syncthreads();
    }

    // epilogue
#pragma unroll
    for (int mt = 0; mt < MT; mt++) {
#pragma unroll
        for (int nt = 0; nt < NT; nt++) {
            int m = m0 + wm0 + mt * 16 + qr;
            int n = n0 + wn0 + nt * 8 + qc * 2;
            float v0 = apply_epi(c[mt][nt][0], epi, p1, x2, m, n, N);
            float v1 = apply_epi(c[mt][nt][1], epi, p1, x2, m, n + 1, N);
            float v2 = apply_epi(c[mt][nt][2], epi, p1, x2, m + 8, n, N);
            float v3 = apply_epi(c[mt][nt][3], epi, p1, x2, m + 8, n + 1, N);
            if (sON == 1) {
                *(float2*)(O + (long long)m * sOM + n)       = make_float2(v0, v1);
                *(float2*)(O + (long long)(m + 8) * sOM + n) = make_float2(v2, v3);
            } else {
                O[(long long)m * sOM + (long long)n * sON]           = v0;
                O[(long long)m * sOM + (long long)(n + 1) * sON]     = v1;
                O[(long long)(m + 8) * sOM + (long long)n * sON]     = v2;
                O[(long long)(m + 8) * sOM + (long long)(n + 1) * sON] = v3;
            }
        }
    }
#undef LOAD_T
#undef STORE_T
}

// ---------------- E1 ----------------
__global__ __launch_bounds__(256) void e1_k(
    const float* __restrict__ kc, const float* __restrict__ kl,
    const float* __restrict__ asig, float* __restrict__ am, float* __restrict__ bm)
{
    int gw = (int)((blockIdx.x * blockDim.x + threadIdx.x) >> 5);
    int lane = threadIdx.x & 31;
    long long base = (long long)gw * 64;
    float k1 = kc[base + lane]      + kl[base + lane];
    float k2 = kc[base + lane + 32] + kl[base + lane + 32];
    float ss = k1 * k1 + k2 * k2;
#pragma unroll
    for (int o = 16; o; o >>= 1) ss += __shfl_xor_sync(0xffffffffu, ss, o);
    float inv = 1.f / fmaxf(sqrtf(ss), 1e-12f);
    float n1 = k1 * inv, n2 = k2 * inv;
    am[base + lane]      = -n1;
    am[base + lane + 32] = -n2;
    bm[base + lane]      = n1 * asig[base + lane];
    bm[base + lane + 32] = n2 * asig[base + lane + 32];
}

// ---------------- WKV7 ----------------
#define RS 4
__global__ __launch_bounds__(64) void wkv7_k(const float* __restrict__ rin, float* __restrict__ y)
{
    int blk = blockIdx.x;
    int rs = blk & 3;
    int bh = blk >> 2;
    int b = bh / Hh, h = bh % Hh;
    long long base = (long long)b * Tt * Cc + (long long)h * 64;

    int tid = threadIdx.x;
    int lr = tid >> 2, jc = tid & 3;
    int i = rs * 16 + lr;
    int jb = jc << 4;

    __shared__ __align__(16) float sh[2][384];

#pragma unroll
    for (int q = 0; q < 6; q++)
        sh[0][q * 64 + tid] = rin[(long long)q * BTCll + base + tid];
    __syncthreads();

    ull S2[8];
#pragma unroll
    for (int u = 0; u < 8; u++) S2[u] = 0ull;
    float sa = 0.f;

    for (int t = 0; t < Tt; t++) {
        int cur = t & 1, nxt = cur ^ 1;
        float pf[6];
        if (t + 1 < Tt) {
            long long off = base + (long long)(t + 1) * Cc;
#pragma unroll
            for (int q = 0; q < 6; q++)
                pf[q] = rin[(long long)q * BTCll + off + tid];
        } else {
#pragma unroll
            for (int q = 0; q < 6; q++) pf[q] = 0.f;
        }

        const float* sb = &sh[cur][0];
        float vi = sb[3 * 64 + i];
        ull vi2 = pk2(vi), sa2 = pk2(sa);

        const ulonglong2* wp = (const ulonglong2*)(sb + 1 * 64 + jb);
        const ulonglong2* kp = (const ulonglong2*)(sb + 2 * 64 + jb);
        const ulonglong2* bp = (const ulonglong2*)(sb + 5 * 64 + jb);
        const ulonglong2* rp = (const ulonglong2*)(sb + 0 * 64 + jb);

#pragma unroll
        for (int q = 0; q < 4; q++) {
            ulonglong2 wv = wp[q], kv = kp[q], bv = bp[q];
            ull d0 = mul2(vi2, kv.x);
            fma2(d0, sa2, bv.x);
            fma2(d0, S2[2 * q], wv.x);
            S2[2 * q] = d0;
            ull d1 = mul2(vi2, kv.y);
            fma2(d1, sa2, bv.y);
            fma2(d1, S2[2 * q + 1], wv.y);
            S2[2 * q + 1] = d1;
        }

        ull ya = 0ull, yb = 0ull;
#pragma unroll
        for (int q = 0; q < 4; q++) {
            ulonglong2 rv = rp[q];
            fma2(ya, S2[2 * q], rv.x);
            fma2(yb, S2[2 * q + 1], rv.y);
        }

        float* sn = &sh[nxt][0];
#pragma unroll
        for (int q = 0; q < 6; q++) sn[q * 64 + tid] = pf[q];
        __syncthreads();

        const ulonglong2* ap = (const ulonglong2*)(&sh[nxt][4 * 64 + jb]);
        ull za = 0ull, zb = 0ull;
#pragma unroll
        for (int q = 0; q < 4; q++) {
            ulonglong2 av = ap[q];
            fma2(za, S2[2 * q], av.x);
            fma2(zb, S2[2 * q + 1], av.y);
        }

        float yv = (lo2(ya) + hi2(ya)) + (lo2(yb) + hi2(yb));
        float sv = (lo2(za) + hi2(za)) + (lo2(zb) + hi2(zb));
        yv += __shfl_xor_sync(0xffffffffu, yv, 1);
        sv += __shfl_xor_sync(0xffffffffu, sv, 1);
        yv += __shfl_xor_sync(0xffffffffu, yv, 2);
        sv += __shfl_xor_sync(0xffffffffu, sv, 2);
        sa = sv;
        if (jc == 0)
            y[base + (long long)t * Cc + i] = yv;
    }
}

// ---------------- E2 ----------------
__global__ __launch_bounds__(768) void e2_k(
    const float* __restrict__ y,
    const float* __restrict__ rr, const float* __restrict__ kk, const float* __restrict__ vv,
    const float* __restrict__ gg, const float* __restrict__ faaaa,
    const float* __restrict__ lnw, float* __restrict__ yg)
{
    long long base = (long long)blockIdx.x * Cc;
    int c = threadIdx.x;
    int w = c >> 5, h = c >> 6, j = c & 63, lane = c & 31;
    float yv = y[base + c];
    float rv = rr[base + c], kv = kk[base + c], vV = vv[base + c];
    float s1 = yv * yv;
    float s2 = rv * kv * faaaa[h * 64 + j];
#pragma unroll
    for (int o = 16; o; o >>= 1) {
        s1 += __shfl_xor_sync(0xffffffffu, s1, o);
        s2 += __shfl_xor_sync(0xffffffffu, s2, o);
    }
    __shared__ float sh1[24], sh2[24];
    if (lane == 0) { sh1[w] = s1; sh2[w] = s2; }
    __syncthreads();
    float tot = 0.f;
#pragma unroll
    for (int q = 0; q < 24; q++) tot += sh1[q];
    float scale = rsqrtf(tot * (1.f / 768.f) + 1e-5f);
    float rk = sh2[h * 2] + sh2[h * 2 + 1];
    float yo = yv * scale * lnw[c] + rk * vV;
    yg[base + c] = yo * gg[base + c];
}

// ---------------- launch ----------------
static inline long long pdiff(const void* p, const void* base) {
    return (long long)((const float*)p - (const float*)base);
}

extern "C" void kernel_launch(void* const* d_in, const int* in_sizes, int n_in,
                              void* d_out, int out_size)
{
    (void)in_sizes; (void)n_in; (void)out_size;
    const float* x       = (const float*)d_in[0];
    const float* tmaa_r  = (const float*)d_in[2];
    const float* tmaa_w  = (const float*)d_in[3];
    const float* tmaa_k  = (const float*)d_in[4];
    const float* tmaa_v  = (const float*)d_in[5];
    const float* tmaa_a  = (const float*)d_in[6];
    const float* tmaa_g  = (const float*)d_in[7];
    const float* tdecay  = (const float*)d_in[8];
    const float* faaaa   = (const float*)d_in[9];
    const float* taaaaa  = (const float*)d_in[10];
    const float* maa_w1  = (const float*)d_in[11];
    const float* maa_w2  = (const float*)d_in[12];
    const float* dec_w1  = (const float*)d_in[13];
    const float* dec_w2  = (const float*)d_in[14];
    const float* aaa_w1  = (const float*)d_in[15];
    const float* aaa_w2  = (const float*)d_in[16];
    const float* kkk_w1  = (const float*)d_in[17];
    const float* kkk_w2  = (const float*)d_in[18];
    const float* gate_w1 = (const float*)d_in[19];
    const float* gate_w2 = (const float*)d_in[20];
    const float* w_key   = (const float*)d_in[21];
    const float* w_val   = (const float*)d_in[22];
    const float* w_rec   = (const float*)d_in[23];
    const float* w_out   = (const float*)d_in[24];
    const float* lnw     = (const float*)d_in[25];
    float* out = (float*)d_out;

    float* ws = 0;
    cudaGetSymbolAddress((void**)&ws, g_ws);

    float* TM  = ws + WS_TM;
    float* XB  = ws + WS_XB;
    float* H1  = ws + WS_H1;
    float* RIN = ws + WS_RIN;
    float* KL  = ws + WS_KL;
    float* AS  = ws + WS_AS;
    float* GT  = ws + WS_GT;
    float* Y   = ws + WS_Y;
    float* YG  = ws + WS_YG;

    // 1) TM = tanh(maa_w1 @ x): M=384, K=768
    {
        ZMap zm = {};
        for (int b = 0; b < 2; b++) {
            zm.b[b] = (long long)b * CTll;
            zm.o[b] = (long long)b * 384 * Tt;
            zm.epi[b] = EPI_TANH;
        }
        gemm_k<128><<<dim3(32, 3, 2), 256>>>(maa_w1, 768, 1, x, Tt, 1, TM, Tt, 1,
                                             2048, 768, 0, 0, zm);
    }

    // 2) MIX: z = n*2+b, M=768, K=64, A col-major
    {
        ZMap zm = {};
        const float* tmaas[6] = {tmaa_r, tmaa_w, tmaa_k, tmaa_v, tmaa_a, tmaa_g};
        for (int n = 0; n < 6; n++)
            for (int b = 0; b < 2; b++) {
                int z = n * 2 + b;
                zm.a[z]  = (long long)n * 64 * Cc;
                zm.b[z]  = (long long)b * 384 * Tt + (long long)n * 64 * Tt;
                zm.o[z]  = (long long)n * BTCll + (long long)b * CTll;
                zm.x1[z] = pdiff(tmaas[n], tmaa_r);
                zm.x2[z] = (long long)b * CTll;
                zm.epi[z] = EPI_MIX;
            }
        gemm_k<128><<<dim3(32, 6, 12), 256>>>(maa_w2, 1, Cc, TM, Tt, 1, XB, Tt, 1,
                                              2048, 64, tmaa_r, x, zm);
    }

    // 3) convs (r,k,v): z = q*4+g*2+b, M=384, K=384
    {
        ZMap zm = {};
        long long qd[3] = {0, pdiff(w_key, w_rec), pdiff(w_val, w_rec)};
        const int xbi[3] = {0, 2, 3};
        const int rio[3] = {0, 2, 3};
        for (int q = 0; q < 3; q++)
            for (int g = 0; g < 2; g++)
                for (int b = 0; b < 2; b++) {
                    int z = q * 4 + g * 2 + b;
                    zm.a[z] = qd[q] + (long long)g * 384 * 384;
                    zm.b[z] = (long long)xbi[q] * BTCll + (long long)b * CTll + (long long)g * 384 * Tt;
                    zm.o[z] = (long long)rio[q] * BTCll + (long long)b * Tt * Cc + g * 384;
                    zm.epi[z] = EPI_NONE;
                }
        gemm_k<128><<<dim3(32, 3, 12), 256>>>(w_rec, 384, 1, XB, Tt, 1, RIN, 1, Cc,
                                              2048, 384, 0, 0, zm);
    }

    // 4) lora stage1 (dec,kkk,aaa): M=64, K=768
    {
        ZMap zm = {};
        long long qd[3] = {0, pdiff(kkk_w1, dec_w1), pdiff(aaa_w1, dec_w1)};
        const int sl[3] = {1, 2, 4};
        for (int q = 0; q < 3; q++)
            for (int b = 0; b < 2; b++) {
                int z = q * 2 + b;
                zm.a[z] = qd[q];
                zm.b[z] = (long long)sl[q] * BTCll + (long long)b * CTll;
                zm.o[z] = (long long)q * (2LL * 64 * Tt) + (long long)b * 64 * Tt;
                zm.epi[z] = EPI_TANH;
            }
        gemm_k<64><<<dim3(32, 1, 6), 256>>>(dec_w1, 768, 1, XB, Tt, 1, H1, Tt, 1,
                                            2048, 768, 0, 0, zm);
    }

    // 5) gate stage1: M=192, K=768
    {
        ZMap zm = {};
        for (int b = 0; b < 2; b++) {
            zm.b[b] = 5LL * BTCll + (long long)b * CTll;
            zm.o[b] = (long long)b * 192 * Tt;
            zm.epi[b] = EPI_TANH;
        }
        gemm_k<64><<<dim3(32, 3, 2), 256>>>(gate_w1, 768, 1, XB, Tt, 1, TM, Tt, 1,
                                            2048, 768, 0, 0, zm);
    }

    // 6) lora stage2: M=768, K=64, per-z epilogue
    {
        ZMap zm = {};
        long long qd[3] = {0, pdiff(kkk_w2, dec_w2), pdiff(aaa_w2, dec_w2)};
        long long od[3] = {WS_RIN + BTCll, WS_KL, WS_AS};
        const int ep[3] = {EPI_DECAY, EPI_NONE, EPI_SIG};
        long long xd[3] = {0, 0, pdiff(taaaaa, tdecay)};
        for (int q = 0; q < 3; q++)
            for (int b = 0; b < 2; b++) {
                int z = q * 2 + b;
                zm.a[z]  = qd[q];
                zm.b[z]  = (long long)q * (2LL * 64 * Tt) + (long long)b * 64 * Tt;
                zm.o[z]  = od[q] + (long long)b * Tt * Cc;
                zm.x1[z] = xd[q];
                zm.epi[z] = ep[q];
            }
        gemm_k<128><<<dim3(32, 6, 6), 256>>>(dec_w2, 64, 1, H1, Tt, 1, ws, 1, Cc,
                                             2048, 64, tdecay, 0, zm);
    }

    // 7) gate stage2: M=768, K=192
    {
        ZMap zm = {};
        for (int b = 0; b < 2; b++) {
            zm.b[b] = (long long)b * 192 * Tt;
            zm.o[b] = (long long)b * Tt * Cc;
            zm.epi[b] = EPI_NONE;
        }
        gemm_k<128><<<dim3(32, 6, 2), 256>>>(gate_w2, 192, 1, TM, Tt, 1, GT, 1, Cc,
                                             2048, 192, 0, 0, zm);
    }

    // 8) E1
    e1_k<<<(Bb * Tt * Hh) / 8, 256>>>(RIN + 2 * BTCll, KL, AS,
                                      RIN + 4 * BTCll, RIN + 5 * BTCll);

    // 9) WKV7
    wkv7_k<<<Bb * Hh * RS, 64>>>(RIN, Y);

    // 10) E2
    e2_k<<<Bb * Tt, 768>>>(Y, RIN, RIN + 2 * BTCll, RIN + 3 * BTCll,
                           GT, faaaa, lnw, YG);

    // 11) output conv: M=384, K=384
    {
        ZMap zm = {};
        for (int g = 0; g < 2; g++)
            for (int b = 0; b < 2; b++) {
                int z = g * 2 + b;
                zm.a[z] = (long long)g * 384 * 384;
                zm.b[z] = (long long)b * Tt * Cc + g * 384;
                zm.o[z] = (long long)b * CTll + (long long)g * 384 * Tt;
                zm.epi[z] = EPI_NONE;
            }
        gemm_k<128><<<dim3(32, 3, 4), 256>>>(w_out, 384, 1, YG, 1, Cc, out, Tt, 1,
                                             2048, 384, 0, 0, zm);
    }
}

// round 5
// speedup vs baseline: 1.1042x; 1.0448x over previous
#include <cuda_runtime.h>
#include <math.h>

#define Bb 2
#define Tt 2048
#define Cc 768
#define Hh 12

typedef unsigned long long ull;

static const long long CTll  = (long long)Cc * Tt;
static const long long BTCll = (long long)Bb * Tt * Cc;

// ---------------- workspace ----------------
#define WS_TM 0LL
#define WS_XB 1572864LL
#define WS_H1 20447232LL
#define WS_RIN 21233664LL
#define WS_KL 40108032LL
#define WS_AS 43253760LL
#define WS_GT 46399488LL
#define WS_Y  49545216LL
#define WS_YG 52690944LL
__device__ float g_ws[55836672];

// ---------------- f32x2 helpers (WKV) ----------------
__device__ __forceinline__ void fma2(ull &d, ull a, ull b) {
    asm("fma.rn.f32x2 %0, %1, %2, %0;" : "+l"(d) : "l"(a), "l"(b));
}
__device__ __forceinline__ ull mul2(ull a, ull b) {
    ull d; asm("mul.rn.f32x2 %0, %1, %2;" : "=l"(d) : "l"(a), "l"(b)); return d;
}
__device__ __forceinline__ ull pk2(float v) {
    ull r; unsigned u = __float_as_uint(v);
    asm("mov.b64 %0, {%1, %1};" : "=l"(r) : "r"(u));
    return r;
}
__device__ __forceinline__ float lo2(ull p) { return __uint_as_float((unsigned)p); }
__device__ __forceinline__ float hi2(ull p) { return __uint_as_float((unsigned)(p >> 32)); }

// ---------------- tf32 / mma helpers ----------------
__device__ __forceinline__ void spl(float v, float &hi, float &lo) {
    unsigned u = __float_as_uint(v) & 0xFFFFE000u;
    hi = __uint_as_float(u);
    lo = v - hi;
}
__device__ __forceinline__ void mma8(float c[4], const float a[4], float b0, float b1) {
    asm volatile("mma.sync.aligned.m16n8k8.row.col.f32.tf32.tf32.f32 "
        "{%0,%1,%2,%3}, {%4,%5,%6,%7}, {%8,%9}, {%0,%1,%2,%3};"
        : "+f"(c[0]), "+f"(c[1]), "+f"(c[2]), "+f"(c[3])
        : "r"(__float_as_uint(a[0])), "r"(__float_as_uint(a[1])),
          "r"(__float_as_uint(a[2])), "r"(__float_as_uint(a[3])),
          "r"(__float_as_uint(b0)), "r"(__float_as_uint(b1)));
}
__device__ __forceinline__ void cpa16(float* dst, const float* src) {
    unsigned d = (unsigned)__cvta_generic_to_shared(dst);
    asm volatile("cp.async.cg.shared.global [%0], [%1], 16;" :: "r"(d), "l"(src));
}
#define CP_COMMIT asm volatile("cp.async.commit_group;")
#define CP_WAIT1  asm volatile("cp.async.wait_group 1;")

// ---------------- GEMM (tensor core, 3xTF32, cp.async pipeline) ----------------
enum { EPI_NONE = 0, EPI_TANH = 1, EPI_MIX = 2, EPI_DECAY = 3, EPI_SIG = 4 };

struct ZMap {
    long long a[12], b[12], o[12], x1[12], x2[12];
    int epi[12];
};

__device__ __forceinline__ float apply_epi(float v, int epi, const float* p1,
                                           const float* x2, int m, int n, int N) {
    if (epi == EPI_TANH) {
        v = tanhf(v);
    } else if (epi == EPI_MIX) {
        v = x2[(long long)m * N + n] * (1.f + p1[m] + v);
    } else if (epi == EPI_DECAY) {
        float u = -(p1[m] + v);
        float sp = fmaxf(u, 0.f) + log1pf(expf(-fabsf(u)));
        v = expf(-expf(-sp - 0.5f));
    } else if (epi == EPI_SIG) {
        v = 1.f / (1.f + expf(-(p1[m] + v)));
    }
    return v;
}

// block tile: TILEM x 64, KC=32, 256 threads (8 warps as 2m x 4n),
// warp tile (TILEM/2) x 16
template<int TILEM>
__global__ __launch_bounds__(256, 2) void gemm_k(
    const float* __restrict__ A, int sAM, int sAK,
    const float* __restrict__ Bm, int sBK, int sBN,
    float* __restrict__ O, int sOM, int sON,
    int N, int K,
    const float* __restrict__ aux1, const float* __restrict__ aux2,
    ZMap zm)
{
    constexpr int MT = TILEM / 32;       // 4 or 2 m16-tiles per warp
    constexpr int NT = 2;                // n8-tiles per warp
    constexpr int AP = TILEM + 8;        // col-variant pitch
    constexpr int AELE = TILEM * 36;     // row-variant size (>= col variant 32*AP)
    constexpr int BELE = 32 * 72;        // == 64*36
    constexpr int STG = AELE + BELE;
    constexpr int ACH = (TILEM == 128) ? 4 : 2;

    extern __shared__ float smem[];

    int z = blockIdx.z;
    A  += zm.a[z];
    Bm += zm.b[z];
    O  += zm.o[z];
    const float* p1 = aux1 ? aux1 + zm.x1[z] : (const float*)0;
    const float* x2 = aux2 ? aux2 + zm.x2[z] : (const float*)0;
    const int epi = zm.epi[z];

    const int tid = threadIdx.x;
    const int m0 = blockIdx.y * TILEM, n0 = blockIdx.x * 64;
    const int warp = tid >> 5, lane = tid & 31;
    const int qr = lane >> 2, qc = lane & 3;
    const int wm0 = (warp & 1) * (TILEM / 2);
    const int wn0 = (warp >> 1) * 16;

    const bool arow = (sAK == 1);
    const bool bnc  = (sBN == 1);

    // loader indices
    const int la_m = (TILEM == 128) ? (tid >> 1) : (tid >> 2);
    const int la_k = (TILEM == 128) ? ((tid & 1) * 16) : ((tid & 3) * 8);
    const int lc_k = tid >> 3;
    const int lc_m = (TILEM == 128) ? ((tid & 7) * 16) : ((tid & 7) * 8);
    const int lb_k = tid >> 3, lb_n = (tid & 7) * 8;
    const int lb2_n = tid >> 2, lb2_k = (tid & 3) * 8;

    auto issue = [&](int kt) {
        float* Sa = smem + (kt % 3) * STG;
        float* Sb = Sa + AELE;
        int k0 = kt * 32;
        if (arow) {
            const float* src = A + (long long)(m0 + la_m) * sAM + k0 + la_k;
            float* dst = Sa + la_m * 36 + la_k;
#pragma unroll
            for (int j = 0; j < ACH; j++) cpa16(dst + 4 * j, src + 4 * j);
        } else {
            const float* src = A + (long long)(k0 + lc_k) * sAK + m0 + lc_m;
            float* dst = Sa + lc_k * AP + lc_m;
#pragma unroll
            for (int j = 0; j < ACH; j++) cpa16(dst + 4 * j, src + 4 * j);
        }
        if (bnc) {
            const float* src = Bm + (long long)(k0 + lb_k) * sBK + n0 + lb_n;
            float* dst = Sb + lb_k * 72 + lb_n;
#pragma unroll
            for (int j = 0; j < 2; j++) cpa16(dst + 4 * j, src + 4 * j);
        } else {
            const float* src = Bm + (long long)(n0 + lb2_n) * sBN + k0 + lb2_k;
            float* dst = Sb + lb2_n * 36 + lb2_k;
#pragma unroll
            for (int j = 0; j < 2; j++) cpa16(dst + 4 * j, src + 4 * j);
        }
    };

    float c[MT][NT][4];
#pragma unroll
    for (int mt = 0; mt < MT; mt++)
#pragma unroll
        for (int nt = 0; nt < NT; nt++)
#pragma unroll
            for (int r = 0; r < 4; r++) c[mt][nt][r] = 0.f;

    const int nk = K >> 5;
    issue(0); CP_COMMIT;
    if (nk > 1) issue(1);
    CP_COMMIT;

    for (int kt = 0; kt < nk; kt++) {
        CP_WAIT1;
        __syncthreads();
        if (kt + 2 < nk) issue(kt + 2);
        CP_COMMIT;

        const float* Sa = smem + (kt % 3) * STG;
        const float* Sb = Sa + AELE;

#pragma unroll
        for (int s = 0; s < 4; s++) {
            const int ks = s * 8 + qc;
            float bh[NT][2], bl[NT][2];
#pragma unroll
            for (int nt = 0; nt < NT; nt++) {
                int n = wn0 + nt * 8 + qr;
                float b0, b1;
                if (bnc) { b0 = Sb[ks * 72 + n]; b1 = Sb[(ks + 4) * 72 + n]; }
                else     { b0 = Sb[n * 36 + ks]; b1 = Sb[n * 36 + ks + 4]; }
                spl(b0, bh[nt][0], bl[nt][0]);
                spl(b1, bh[nt][1], bl[nt][1]);
            }
#pragma unroll
            for (int mt = 0; mt < MT; mt++) {
                int m = wm0 + mt * 16 + qr;
                float a0, a1, a2, a3;
                if (arow) {
                    a0 = Sa[m * 36 + ks];       a1 = Sa[(m + 8) * 36 + ks];
                    a2 = Sa[m * 36 + ks + 4];   a3 = Sa[(m + 8) * 36 + ks + 4];
                } else {
                    a0 = Sa[ks * AP + m];       a1 = Sa[ks * AP + m + 8];
                    a2 = Sa[(ks + 4) * AP + m]; a3 = Sa[(ks + 4) * AP + m + 8];
                }
                float ah[4], al[4];
                spl(a0, ah[0], al[0]); spl(a1, ah[1], al[1]);
                spl(a2, ah[2], al[2]); spl(a3, ah[3], al[3]);
#pragma unroll
                for (int nt = 0; nt < NT; nt++) {
                    mma8(c[mt][nt], ah, bh[nt][0], bh[nt][1]);
                    mma8(c[mt][nt], al, bh[nt][0], bh[nt][1]);
                    mma8(c[mt][nt], ah, bl[nt][0], bl[nt][1]);
                }
            }
        }
    }

    // epilogue
#pragma unroll
    for (int mt = 0; mt < MT; mt++) {
#pragma unroll
        for (int nt = 0; nt < NT; nt++) {
            int m = m0 + wm0 + mt * 16 + qr;
            int n = n0 + wn0 + nt * 8 + qc * 2;
            float v0 = apply_epi(c[mt][nt][0], epi, p1, x2, m, n, N);
            float v1 = apply_epi(c[mt][nt][1], epi, p1, x2, m, n + 1, N);
            float v2 = apply_epi(c[mt][nt][2], epi, p1, x2, m + 8, n, N);
            float v3 = apply_epi(c[mt][nt][3], epi, p1, x2, m + 8, n + 1, N);
            if (sON == 1) {
                *(float2*)(O + (long long)m * sOM + n)       = make_float2(v0, v1);
                *(float2*)(O + (long long)(m + 8) * sOM + n) = make_float2(v2, v3);
            } else {
                O[(long long)m * sOM + (long long)n * sON]             = v0;
                O[(long long)m * sOM + (long long)(n + 1) * sON]       = v1;
                O[(long long)(m + 8) * sOM + (long long)n * sON]       = v2;
                O[(long long)(m + 8) * sOM + (long long)(n + 1) * sON] = v3;
            }
        }
    }
}

// ---------------- E1 ----------------
__global__ __launch_bounds__(256) void e1_k(
    const float* __restrict__ kc, const float* __restrict__ kl,
    const float* __restrict__ asig, float* __restrict__ am, float* __restrict__ bm)
{
    int gw = (int)((blockIdx.x * blockDim.x + threadIdx.x) >> 5);
    int lane = threadIdx.x & 31;
    long long base = (long long)gw * 64;
    float k1 = kc[base + lane]      + kl[base + lane];
    float k2 = kc[base + lane + 32] + kl[base + lane + 32];
    float ss = k1 * k1 + k2 * k2;
#pragma unroll
    for (int o = 16; o; o >>= 1) ss += __shfl_xor_sync(0xffffffffu, ss, o);
    float inv = 1.f / fmaxf(sqrtf(ss), 1e-12f);
    float n1 = k1 * inv, n2 = k2 * inv;
    am[base + lane]      = -n1;
    am[base + lane + 32] = -n2;
    bm[base + lane]      = n1 * asig[base + lane];
    bm[base + lane + 32] = n2 * asig[base + lane + 32];
}

// ---------------- WKV7 ----------------
#define RS 4
__global__ __launch_bounds__(64) void wkv7_k(const float* __restrict__ rin, float* __restrict__ y)
{
    int blk = blockIdx.x;
    int rs = blk & 3;
    int bh = blk >> 2;
    int b = bh / Hh, h = bh % Hh;
    long long base = (long long)b * Tt * Cc + (long long)h * 64;

    int tid = threadIdx.x;
    int lr = tid >> 2, jc = tid & 3;
    int i = rs * 16 + lr;
    int jb = jc << 4;

    __shared__ __align__(16) float sh[2][384];

#pragma unroll
    for (int q = 0; q < 6; q++)
        sh[0][q * 64 + tid] = rin[(long long)q * BTCll + base + tid];
    __syncthreads();

    ull S2[8];
#pragma unroll
    for (int u = 0; u < 8; u++) S2[u] = 0ull;
    float sa = 0.f;

    for (int t = 0; t < Tt; t++) {
        int cur = t & 1, nxt = cur ^ 1;
        float pf[6];
        if (t + 1 < Tt) {
            long long off = base + (long long)(t + 1) * Cc;
#pragma unroll
            for (int q = 0; q < 6; q++)
                pf[q] = rin[(long long)q * BTCll + off + tid];
        } else {
#pragma unroll
            for (int q = 0; q < 6; q++) pf[q] = 0.f;
        }

        const float* sb = &sh[cur][0];
        float vi = sb[3 * 64 + i];
        ull vi2 = pk2(vi), sa2 = pk2(sa);

        const ulonglong2* wp = (const ulonglong2*)(sb + 1 * 64 + jb);
        const ulonglong2* kp = (const ulonglong2*)(sb + 2 * 64 + jb);
        const ulonglong2* bp = (const ulonglong2*)(sb + 5 * 64 + jb);
        const ulonglong2* rp = (const ulonglong2*)(sb + 0 * 64 + jb);

#pragma unroll
        for (int q = 0; q < 4; q++) {
            ulonglong2 wv = wp[q], kv = kp[q], bv = bp[q];
            ull d0 = mul2(vi2, kv.x);
            fma2(d0, sa2, bv.x);
            fma2(d0, S2[2 * q], wv.x);
            S2[2 * q] = d0;
            ull d1 = mul2(vi2, kv.y);
            fma2(d1, sa2, bv.y);
            fma2(d1, S2[2 * q + 1], wv.y);
            S2[2 * q + 1] = d1;
        }

        ull ya = 0ull, yb = 0ull;
#pragma unroll
        for (int q = 0; q < 4; q++) {
            ulonglong2 rv = rp[q];
            fma2(ya, S2[2 * q], rv.x);
            fma2(yb, S2[2 * q + 1], rv.y);
        }

        float* sn = &sh[nxt][0];
#pragma unroll
        for (int q = 0; q < 6; q++) sn[q * 64 + tid] = pf[q];
        __syncthreads();

        const ulonglong2* ap = (const ulonglong2*)(&sh[nxt][4 * 64 + jb]);
        ull za = 0ull, zb = 0ull;
#pragma unroll
        for (int q = 0; q < 4; q++) {
            ulonglong2 av = ap[q];
            fma2(za, S2[2 * q], av.x);
            fma2(zb, S2[2 * q + 1], av.y);
        }

        float yv = (lo2(ya) + hi2(ya)) + (lo2(yb) + hi2(yb));
        float sv = (lo2(za) + hi2(za)) + (lo2(zb) + hi2(zb));
        yv += __shfl_xor_sync(0xffffffffu, yv, 1);
        sv += __shfl_xor_sync(0xffffffffu, sv, 1);
        yv += __shfl_xor_sync(0xffffffffu, yv, 2);
        sv += __shfl_xor_sync(0xffffffffu, sv, 2);
        sa = sv;
        if (jc == 0)
            y[base + (long long)t * Cc + i] = yv;
    }
}

// ---------------- E2 ----------------
__global__ __launch_bounds__(768) void e2_k(
    const float* __restrict__ y,
    const float* __restrict__ rr, const float* __restrict__ kk, const float* __restrict__ vv,
    const float* __restrict__ gg, const float* __restrict__ faaaa,
    const float* __restrict__ lnw, float* __restrict__ yg)
{
    long long base = (long long)blockIdx.x * Cc;
    int c = threadIdx.x;
    int w = c >> 5, h = c >> 6, j = c & 63, lane = c & 31;
    float yv = y[base + c];
    float rv = rr[base + c], kv = kk[base + c], vV = vv[base + c];
    float s1 = yv * yv;
    float s2 = rv * kv * faaaa[h * 64 + j];
#pragma unroll
    for (int o = 16; o; o >>= 1) {
        s1 += __shfl_xor_sync(0xffffffffu, s1, o);
        s2 += __shfl_xor_sync(0xffffffffu, s2, o);
    }
    __shared__ float sh1[24], sh2[24];
    if (lane == 0) { sh1[w] = s1; sh2[w] = s2; }
    __syncthreads();
    float tot = 0.f;
#pragma unroll
    for (int q = 0; q < 24; q++) tot += sh1[q];
    float scale = rsqrtf(tot * (1.f / 768.f) + 1e-5f);
    float rk = sh2[h * 2] + sh2[h * 2 + 1];
    float yo = yv * scale * lnw[c] + rk * vV;
    yg[base + c] = yo * gg[base + c];
}

// ---------------- launch ----------------
static inline long long pdiff(const void* p, const void* base) {
    return (long long)((const float*)p - (const float*)base);
}

#define SMEM128 ((128 * 36 + 32 * 72) * 3 * 4)
#define SMEM64  ((64 * 36 + 32 * 72) * 3 * 4)

extern "C" void kernel_launch(void* const* d_in, const int* in_sizes, int n_in,
                              void* d_out, int out_size)
{
    (void)in_sizes; (void)n_in; (void)out_size;
    const float* x       = (const float*)d_in[0];
    const float* tmaa_r  = (const float*)d_in[2];
    const float* tmaa_w  = (const float*)d_in[3];
    const float* tmaa_k  = (const float*)d_in[4];
    const float* tmaa_v  = (const float*)d_in[5];
    const float* tmaa_a  = (const float*)d_in[6];
    const float* tmaa_g  = (const float*)d_in[7];
    const float* tdecay  = (const float*)d_in[8];
    const float* faaaa   = (const float*)d_in[9];
    const float* taaaaa  = (const float*)d_in[10];
    const float* maa_w1  = (const float*)d_in[11];
    const float* maa_w2  = (const float*)d_in[12];
    const float* dec_w1  = (const float*)d_in[13];
    const float* dec_w2  = (const float*)d_in[14];
    const float* aaa_w1  = (const float*)d_in[15];
    const float* aaa_w2  = (const float*)d_in[16];
    const float* kkk_w1  = (const float*)d_in[17];
    const float* kkk_w2  = (const float*)d_in[18];
    const float* gate_w1 = (const float*)d_in[19];
    const float* gate_w2 = (const float*)d_in[20];
    const float* w_key   = (const float*)d_in[21];
    const float* w_val   = (const float*)d_in[22];
    const float* w_rec   = (const float*)d_in[23];
    const float* w_out   = (const float*)d_in[24];
    const float* lnw     = (const float*)d_in[25];
    float* out = (float*)d_out;

    static int attr_done = 0;
    if (!attr_done) {
        cudaFuncSetAttribute(gemm_k<128>, cudaFuncAttributeMaxDynamicSharedMemorySize, SMEM128);
        cudaFuncSetAttribute(gemm_k<64>,  cudaFuncAttributeMaxDynamicSharedMemorySize, SMEM64);
        attr_done = 1;
    }

    float* ws = 0;
    cudaGetSymbolAddress((void**)&ws, g_ws);

    float* TM  = ws + WS_TM;
    float* XB  = ws + WS_XB;
    float* H1  = ws + WS_H1;
    float* RIN = ws + WS_RIN;
    float* KL  = ws + WS_KL;
    float* AS  = ws + WS_AS;
    float* GT  = ws + WS_GT;
    float* Y   = ws + WS_Y;
    float* YG  = ws + WS_YG;

    // 1) TM = tanh(maa_w1 @ x): M=384, K=768
    {
        ZMap zm = {};
        for (int b = 0; b < 2; b++) {
            zm.b[b] = (long long)b * CTll;
            zm.o[b] = (long long)b * 384 * Tt;
            zm.epi[b] = EPI_TANH;
        }
        gemm_k<128><<<dim3(32, 3, 2), 256, SMEM128>>>(maa_w1, 768, 1, x, Tt, 1, TM, Tt, 1,
                                                      2048, 768, 0, 0, zm);
    }

    // 2) MIX: z = n*2+b, M=768, K=64, A col-major
    {
        ZMap zm = {};
        const float* tmaas[6] = {tmaa_r, tmaa_w, tmaa_k, tmaa_v, tmaa_a, tmaa_g};
        for (int n = 0; n < 6; n++)
            for (int b = 0; b < 2; b++) {
                int z = n * 2 + b;
                zm.a[z]  = (long long)n * 64 * Cc;
                zm.b[z]  = (long long)b * 384 * Tt + (long long)n * 64 * Tt;
                zm.o[z]  = (long long)n * BTCll + (long long)b * CTll;
                zm.x1[z] = pdiff(tmaas[n], tmaa_r);
                zm.x2[z] = (long long)b * CTll;
                zm.epi[z] = EPI_MIX;
            }
        gemm_k<128><<<dim3(32, 6, 12), 256, SMEM128>>>(maa_w2, 1, Cc, TM, Tt, 1, XB, Tt, 1,
                                                       2048, 64, tmaa_r, x, zm);
    }

    // 3) convs (r,k,v): z = q*4+g*2+b, M=384, K=384
    {
        ZMap zm = {};
        long long qd[3] = {0, pdiff(w_key, w_rec), pdiff(w_val, w_rec)};
        const int xbi[3] = {0, 2, 3};
        const int rio[3] = {0, 2, 3};
        for (int q = 0; q < 3; q++)
            for (int g = 0; g < 2; g++)
                for (int b = 0; b < 2; b++) {
                    int z = q * 4 + g * 2 + b;
                    zm.a[z] = qd[q] + (long long)g * 384 * 384;
                    zm.b[z] = (long long)xbi[q] * BTCll + (long long)b * CTll + (long long)g * 384 * Tt;
                    zm.o[z] = (long long)rio[q] * BTCll + (long long)b * Tt * Cc + g * 384;
                    zm.epi[z] = EPI_NONE;
                }
        gemm_k<128><<<dim3(32, 3, 12), 256, SMEM128>>>(w_rec, 384, 1, XB, Tt, 1, RIN, 1, Cc,
                                                       2048, 384, 0, 0, zm);
    }

    // 4) lora stage1 (dec,kkk,aaa): M=64, K=768
    {
        ZMap zm = {};
        long long qd[3] = {0, pdiff(kkk_w1, dec_w1), pdiff(aaa_w1, dec_w1)};
        const int sl[3] = {1, 2, 4};
        for (int q = 0; q < 3; q++)
            for (int b = 0; b < 2; b++) {
                int z = q * 2 + b;
                zm.a[z] = qd[q];
                zm.b[z] = (long long)sl[q] * BTCll + (long long)b * CTll;
                zm.o[z] = (long long)q * (2LL * 64 * Tt) + (long long)b * 64 * Tt;
                zm.epi[z] = EPI_TANH;
            }
        gemm_k<64><<<dim3(32, 1, 6), 256, SMEM64>>>(dec_w1, 768, 1, XB, Tt, 1, H1, Tt, 1,
                                                    2048, 768, 0, 0, zm);
    }

    // 5) gate stage1: M=192, K=768
    {
        ZMap zm = {};
        for (int b = 0; b < 2; b++) {
            zm.b[b] = 5LL * BTCll + (long long)b * CTll;
            zm.o[b] = (long long)b * 192 * Tt;
            zm.epi[b] = EPI_TANH;
        }
        gemm_k<64><<<dim3(32, 3, 2), 256, SMEM64>>>(gate_w1, 768, 1, XB, Tt, 1, TM, Tt, 1,
                                                    2048, 768, 0, 0, zm);
    }

    // 6) lora stage2: M=768, K=64, per-z epilogue
    {
        ZMap zm = {};
        long long qd[3] = {0, pdiff(kkk_w2, dec_w2), pdiff(aaa_w2, dec_w2)};
        long long od[3] = {WS_RIN + BTCll, WS_KL, WS_AS};
        const int ep[3] = {EPI_DECAY, EPI_NONE, EPI_SIG};
        long long xd[3] = {0, 0, pdiff(taaaaa, tdecay)};
        for (int q = 0; q < 3; q++)
            for (int b = 0; b < 2; b++) {
                int z = q * 2 + b;
                zm.a[z]  = qd[q];
                zm.b[z]  = (long long)q * (2LL * 64 * Tt) + (long long)b * 64 * Tt;
                zm.o[z]  = od[q] + (long long)b * Tt * Cc;
                zm.x1[z] = xd[q];
                zm.epi[z] = ep[q];
            }
        gemm_k<128><<<dim3(32, 6, 6), 256, SMEM128>>>(dec_w2, 64, 1, H1, Tt, 1, ws, 1, Cc,
                                                      2048, 64, tdecay, 0, zm);
    }

    // 7) gate stage2: M=768, K=192
    {
        ZMap zm = {};
        for (int b = 0; b < 2; b++) {
            zm.b[b] = (long long)b * 192 * Tt;
            zm.o[b] = (long long)b * Tt * Cc;
            zm.epi[b] = EPI_NONE;
        }
        gemm_k<128><<<dim3(32, 6, 2), 256, SMEM128>>>(gate_w2, 192, 1, TM, Tt, 1, GT, 1, Cc,
                                                      2048, 192, 0, 0, zm);
    }

    // 8) E1
    e1_k<<<(Bb * Tt * Hh) / 8, 256>>>(RIN + 2 * BTCll, KL, AS,
                                      RIN + 4 * BTCll, RIN + 5 * BTCll);

    // 9) WKV7
    wkv7_k<<<Bb * Hh * RS, 64>>>(RIN, Y);

    // 10) E2
    e2_k<<<Bb * Tt, 768>>>(Y, RIN, RIN + 2 * BTCll, RIN + 3 * BTCll,
                           GT, faaaa, lnw, YG);

    // 11) output conv: M=384, K=384
    {
        ZMap zm = {};
        for (int g = 0; g < 2; g++)
            for (int b = 0; b < 2; b++) {
                int z = g * 2 + b;
                zm.a[z] = (long long)g * 384 * 384;
                zm.b[z] = (long long)b * Tt * Cc + g * 384;
                zm.o[z] = (long long)b * CTll + (long long)g * 384 * Tt;
                zm.epi[z] = EPI_NONE;
            }
        gemm_k<128><<<dim3(32, 3, 4), 256, SMEM128>>>(w_out, 384, 1, YG, 1, Cc, out, Tt, 1,
                                                      2048, 384, 0, 0, zm);
    }
}

// round 6
// speedup vs baseline: 1.2199x; 1.1048x over previous
#include <cuda_runtime.h>
#include <cuda_bf16.h>
#include <math.h>

#define Bb 2
#define Tt 2048
#define Cc 768
#define Hh 12

typedef unsigned long long ull;
typedef long long ll;

static const ll CTll  = (ll)Cc * Tt;
static const ll BTCll = (ll)Bb * Tt * Cc;

// ---------------- workspace ----------------
#define WS_XP   0LL          // x planes / later reused as YG planes (words)
#define WS_TMP  3145728LL
#define WS_XBP  4718592LL
#define WS_H1P  23592960LL
#define WS_TM2P 24379392LL
#define WS_GT   25165824LL
#define WS_RIN  28311552LL   // 6 x (B,T,C) fp32: r,w,k,v,am,bm
#define WS_KL   47185920LL
#define WS_AS   50331648LL
#define WS_Y    53477376LL
#define WS_WPL  56623104LL   // weight bf16 planes (as float-sized storage)
__device__ float g_ws[58982400];

#define WTOT 2359296   // total weight elems (hi plane size in bf16 elems)

// ---------------- helpers ----------------
__device__ __forceinline__ void fma2(ull &d, ull a, ull b) {
    asm("fma.rn.f32x2 %0, %1, %2, %0;" : "+l"(d) : "l"(a), "l"(b));
}
__device__ __forceinline__ ull mul2(ull a, ull b) {
    ull d; asm("mul.rn.f32x2 %0, %1, %2;" : "=l"(d) : "l"(a), "l"(b)); return d;
}
__device__ __forceinline__ ull pk2(float v) {
    ull r; unsigned u = __float_as_uint(v);
    asm("mov.b64 %0, {%1, %1};" : "=l"(r) : "r"(u));
    return r;
}
__device__ __forceinline__ float lo2(ull p) { return __uint_as_float((unsigned)p); }
__device__ __forceinline__ float hi2(ull p) { return __uint_as_float((unsigned)(p >> 32)); }

__device__ __forceinline__ unsigned pack_hl(float v) {
    __nv_bfloat16 h = __float2bfloat16(v);
    float hf = __bfloat162float(h);
    __nv_bfloat16 l = __float2bfloat16(v - hf);
    return (unsigned)__bfloat16_as_ushort(h) | ((unsigned)__bfloat16_as_ushort(l) << 16);
}
__device__ __forceinline__ unsigned prmt(unsigned a, unsigned b, unsigned s) {
    unsigned d; asm("prmt.b32 %0,%1,%2,%3;" : "=r"(d) : "r"(a), "r"(b), "r"(s)); return d;
}
__device__ __forceinline__ void ldsm4(unsigned &r0, unsigned &r1, unsigned &r2, unsigned &r3,
                                      unsigned saddr) {
    asm volatile("ldmatrix.sync.aligned.m8n8.x4.shared.b16 {%0,%1,%2,%3}, [%4];"
        : "=r"(r0), "=r"(r1), "=r"(r2), "=r"(r3) : "r"(saddr));
}
__device__ __forceinline__ void mma16(float c[4], unsigned a0, unsigned a1, unsigned a2,
                                      unsigned a3, unsigned b0, unsigned b1) {
    asm volatile("mma.sync.aligned.m16n8k16.row.col.f32.bf16.bf16.f32 "
        "{%0,%1,%2,%3}, {%4,%5,%6,%7}, {%8,%9}, {%0,%1,%2,%3};"
        : "+f"(c[0]), "+f"(c[1]), "+f"(c[2]), "+f"(c[3])
        : "r"(a0), "r"(a1), "r"(a2), "r"(a3), "r"(b0), "r"(b1));
}
__device__ __forceinline__ void cpa16(void* dst, const void* src) {
    unsigned d = (unsigned)__cvta_generic_to_shared(dst);
    asm volatile("cp.async.cg.shared.global [%0], [%1], 16;" :: "r"(d), "l"(src));
}
#define CP_COMMIT asm volatile("cp.async.commit_group;")
#define CP_WAIT1  asm volatile("cp.async.wait_group 1;")

// ---------------- prep kernels ----------------
struct PrepTab {
    const float* src[19];
    int dst[19], M[19], K[19], sm[19], sk[19];
};

__global__ __launch_bounds__(256) void prep_w(__nv_bfloat16* hi, PrepTab pt) {
    int sgi = blockIdx.z;
    int idx = blockIdx.x * 256 + threadIdx.x;
    int MK = pt.M[sgi] * pt.K[sgi];
    if (idx >= MK) return;
    int k = idx % pt.K[sgi];
    int m = idx / pt.K[sgi];
    float v = pt.src[sgi][(ll)m * pt.sm[sgi] + (ll)k * pt.sk[sgi]];
    __nv_bfloat16 h = __float2bfloat16(v);
    float hf = __bfloat162float(h);
    __nv_bfloat16 l = __float2bfloat16(v - hf);
    hi[pt.dst[sgi] + idx] = h;
    hi[WTOT + pt.dst[sgi] + idx] = l;
}

__global__ __launch_bounds__(256) void prep_x(const float* __restrict__ x,
                                              unsigned* __restrict__ xp) {
    int idx = blockIdx.x * 256 + threadIdx.x;   // b*C*T + c*T + t
    int t = idx & 2047;
    int rest = idx >> 11;
    int c = rest % Cc, b = rest / Cc;
    xp[(ll)b * 1572864 + (ll)(c >> 1) * 4096 + 2 * t + (c & 1)] = pack_hl(x[idx]);
}

// ---------------- GEMM ----------------
enum { EPI_NONE = 0, EPI_TANH = 1, EPI_MIX = 2, EPI_DECAY = 3, EPI_SIG = 4 };

struct ZMap {
    ll a[12], b[12], o[12], x1[12], x2[12];
    int epi[12];
};

__device__ __forceinline__ float apply_epi(float v, int epi, const float* p1,
                                           const float* x2, int m, int n, int N) {
    if (epi == EPI_TANH) {
        v = tanhf(v);
    } else if (epi == EPI_MIX) {
        v = x2[(ll)m * N + n] * (1.f + p1[m] + v);
    } else if (epi == EPI_DECAY) {
        float u = -(p1[m] + v);
        float sp = fmaxf(u, 0.f) + log1pf(expf(-fabsf(u)));
        v = expf(-expf(-sp - 0.5f));
    } else if (epi == EPI_SIG) {
        v = 1.f / (1.f + expf(-(p1[m] + v)));
    }
    return v;
}

// block tile TILEM x 64, KC=32, 256 threads (8 warps: 2m x 4n)
template<int TILEM>
__global__ __launch_bounds__(256, 2) void gemm_k(
    const __nv_bfloat16* __restrict__ Apl, ll Atot,
    const unsigned* __restrict__ Bpl,
    float* __restrict__ Ob, unsigned* __restrict__ Pb,
    int sOM, int sON, int N, int K, int omode,
    const float* __restrict__ aux1, const float* __restrict__ aux2,
    ZMap zm)
{
    constexpr int MT = TILEM / 32;
    constexpr int ABYTES = TILEM * 80;
    constexpr int STG = 2 * ABYTES + 16 * 544;
    extern __shared__ char smem[];

    const int z = blockIdx.z;
    const __nv_bfloat16* Ahi = Apl + zm.a[z];
    const unsigned* Bg = Bpl + zm.b[z];
    const ll zo = zm.o[z];
    const float* p1 = aux1 ? aux1 + zm.x1[z] : (const float*)0;
    const float* x2 = aux2 ? aux2 + zm.x2[z] : (const float*)0;
    const int epi = zm.epi[z];

    const int tid = threadIdx.x;
    const int m0 = blockIdx.y * TILEM, n0 = blockIdx.x * 64;
    const int warp = tid >> 5, lane = tid & 31;
    const int qr = lane >> 2, qc = lane & 3;
    const int wm0 = (warp & 1) * (TILEM / 2);
    const int wn0 = (warp >> 1) * 16;
    const int rowW = 2 * N;

    unsigned sbase = (unsigned)__cvta_generic_to_shared(smem);

    auto issue = [&](int kt) {
        char* S = smem + (kt % 3) * STG;
        int k0 = kt * 32;
        if (TILEM == 128) {
            int am = tid >> 1, ae = (tid & 1) * 16;
            const __nv_bfloat16* s0 = Ahi + (ll)(m0 + am) * K + k0 + ae;
            char* d0 = S + am * 80 + ae * 2;
            cpa16(d0, s0); cpa16(d0 + 16, s0 + 8);
            cpa16(d0 + ABYTES, s0 + Atot); cpa16(d0 + ABYTES + 16, s0 + Atot + 8);
        } else {
            int am = tid >> 2, ae = (tid & 3) * 8;
            const __nv_bfloat16* s0 = Ahi + (ll)(m0 + am) * K + k0 + ae;
            char* d0 = S + am * 80 + ae * 2;
            cpa16(d0, s0);
            cpa16(d0 + ABYTES, s0 + Atot);
        }
        {
            int kp = tid >> 4, wo = (tid & 15) * 8;
            const unsigned* s = Bg + (ll)(k0 / 2 + kp) * rowW + n0 * 2 + wo;
            char* d = S + 2 * ABYTES + kp * 544 + wo * 4;
            cpa16(d, s); cpa16(d + 16, s + 4);
        }
    };

    float c[MT][2][4];
#pragma unroll
    for (int mt = 0; mt < MT; mt++)
#pragma unroll
        for (int nt = 0; nt < 2; nt++)
#pragma unroll
            for (int r = 0; r < 4; r++) c[mt][nt][r] = 0.f;

    const int nk = K >> 5;
    issue(0); CP_COMMIT;
    if (nk > 1) issue(1);
    CP_COMMIT;

    for (int kt = 0; kt < nk; kt++) {
        CP_WAIT1;
        __syncthreads();
        if (kt + 2 < nk) issue(kt + 2);
        CP_COMMIT;

        char* Sst = smem + (kt % 3) * STG;
        unsigned SAu = sbase + (kt % 3) * STG;
        char* Sb = Sst + 2 * ABYTES;

#pragma unroll
        for (int s = 0; s < 2; s++) {
            unsigned bh[2][2], bl[2][2];
#pragma unroll
            for (int nt = 0; nt < 2; nt++) {
                int n = wn0 + nt * 8 + qr;
                uint2 w01 = *(const uint2*)(Sb + (s * 8 + qc) * 544 + n * 8);
                uint2 w23 = *(const uint2*)(Sb + (s * 8 + qc + 4) * 544 + n * 8);
                bh[nt][0] = prmt(w01.x, w01.y, 0x5410); bl[nt][0] = prmt(w01.x, w01.y, 0x7632);
                bh[nt][1] = prmt(w23.x, w23.y, 0x5410); bl[nt][1] = prmt(w23.x, w23.y, 0x7632);
            }
#pragma unroll
            for (int mt = 0; mt < MT; mt++) {
                unsigned aaddr = SAu + (wm0 + mt * 16 + (lane & 15)) * 80 + (lane >> 4) * 16 + s * 32;
                unsigned h0, h1, h2, h3, l0, l1, l2, l3;
                ldsm4(h0, h1, h2, h3, aaddr);
                ldsm4(l0, l1, l2, l3, aaddr + ABYTES);
#pragma unroll
                for (int nt = 0; nt < 2; nt++) {
                    mma16(c[mt][nt], h0, h1, h2, h3, bh[nt][0], bh[nt][1]);
                    mma16(c[mt][nt], l0, l1, l2, l3, bh[nt][0], bh[nt][1]);
                    mma16(c[mt][nt], h0, h1, h2, h3, bl[nt][0], bl[nt][1]);
                }
            }
        }
    }

#pragma unroll
    for (int mt = 0; mt < MT; mt++) {
#pragma unroll
        for (int nt = 0; nt < 2; nt++) {
            int mA = m0 + wm0 + mt * 16 + qr;
            int nA = n0 + wn0 + nt * 8 + qc * 2;
            float v0 = apply_epi(c[mt][nt][0], epi, p1, x2, mA, nA, N);
            float v1 = apply_epi(c[mt][nt][1], epi, p1, x2, mA, nA + 1, N);
            float v2 = apply_epi(c[mt][nt][2], epi, p1, x2, mA + 8, nA, N);
            float v3 = apply_epi(c[mt][nt][3], epi, p1, x2, mA + 8, nA + 1, N);
            if (omode == 0) {
                float* O = Ob + zo;
                if (sON == 1) {
                    *(float2*)(O + (ll)mA * sOM + nA)       = make_float2(v0, v1);
                    *(float2*)(O + (ll)(mA + 8) * sOM + nA) = make_float2(v2, v3);
                } else {
                    O[(ll)mA * sOM + (ll)nA * sON]             = v0;
                    O[(ll)mA * sOM + (ll)(nA + 1) * sON]       = v1;
                    O[(ll)(mA + 8) * sOM + (ll)nA * sON]       = v2;
                    O[(ll)(mA + 8) * sOM + (ll)(nA + 1) * sON] = v3;
                }
            } else {
                unsigned* P = Pb + zo;
                ll r0 = (ll)(mA >> 1) * rowW + (mA & 1);
                ll r1 = r0 + (ll)4 * rowW;
                P[r0 + 2 * nA]       = pack_hl(v0);
                P[r0 + 2 * (nA + 1)] = pack_hl(v1);
                P[r1 + 2 * nA]       = pack_hl(v2);
                P[r1 + 2 * (nA + 1)] = pack_hl(v3);
            }
        }
    }
}

// ---------------- E1 ----------------
__global__ __launch_bounds__(256) void e1_k(
    const float* __restrict__ kc, const float* __restrict__ kl,
    const float* __restrict__ asig, float* __restrict__ am, float* __restrict__ bm)
{
    int gw = (int)((blockIdx.x * blockDim.x + threadIdx.x) >> 5);
    int lane = threadIdx.x & 31;
    ll base = (ll)gw * 64;
    float k1 = kc[base + lane]      + kl[base + lane];
    float k2 = kc[base + lane + 32] + kl[base + lane + 32];
    float ss = k1 * k1 + k2 * k2;
#pragma unroll
    for (int o = 16; o; o >>= 1) ss += __shfl_xor_sync(0xffffffffu, ss, o);
    float inv = 1.f / fmaxf(sqrtf(ss), 1e-12f);
    float n1 = k1 * inv, n2 = k2 * inv;
    am[base + lane]      = -n1;
    am[base + lane + 32] = -n2;
    bm[base + lane]      = n1 * asig[base + lane];
    bm[base + lane + 32] = n2 * asig[base + lane + 32];
}

// ---------------- WKV7 ----------------
#define RS 4
__global__ __launch_bounds__(64) void wkv7_k(const float* __restrict__ rin, float* __restrict__ y)
{
    int blk = blockIdx.x;
    int rs = blk & 3;
    int bh = blk >> 2;
    int b = bh / Hh, h = bh % Hh;
    ll base = (ll)b * Tt * Cc + (ll)h * 64;

    int tid = threadIdx.x;
    int lr = tid >> 2, jc = tid & 3;
    int i = rs * 16 + lr;
    int jb = jc << 4;

    __shared__ __align__(16) float sh[2][384];

#pragma unroll
    for (int q = 0; q < 6; q++)
        sh[0][q * 64 + tid] = rin[(ll)q * BTCll + base + tid];
    __syncthreads();

    ull S2[8];
#pragma unroll
    for (int u = 0; u < 8; u++) S2[u] = 0ull;
    float sa = 0.f;

    for (int t = 0; t < Tt; t++) {
        int cur = t & 1, nxt = cur ^ 1;
        float pf[6];
        if (t + 1 < Tt) {
            ll off = base + (ll)(t + 1) * Cc;
#pragma unroll
            for (int q = 0; q < 6; q++)
                pf[q] = rin[(ll)q * BTCll + off + tid];
        } else {
#pragma unroll
            for (int q = 0; q < 6; q++) pf[q] = 0.f;
        }

        const float* sb = &sh[cur][0];
        float vi = sb[3 * 64 + i];
        ull vi2 = pk2(vi), sa2 = pk2(sa);

        const ulonglong2* wp = (const ulonglong2*)(sb + 1 * 64 + jb);
        const ulonglong2* kp = (const ulonglong2*)(sb + 2 * 64 + jb);
        const ulonglong2* bp = (const ulonglong2*)(sb + 5 * 64 + jb);
        const ulonglong2* rp = (const ulonglong2*)(sb + 0 * 64 + jb);

#pragma unroll
        for (int q = 0; q < 4; q++) {
            ulonglong2 wv = wp[q], kv = kp[q], bv = bp[q];
            ull d0 = mul2(vi2, kv.x);
            fma2(d0, sa2, bv.x);
            fma2(d0, S2[2 * q], wv.x);
            S2[2 * q] = d0;
            ull d1 = mul2(vi2, kv.y);
            fma2(d1, sa2, bv.y);
            fma2(d1, S2[2 * q + 1], wv.y);
            S2[2 * q + 1] = d1;
        }

        ull ya = 0ull, yb = 0ull;
#pragma unroll
        for (int q = 0; q < 4; q++) {
            ulonglong2 rv = rp[q];
            fma2(ya, S2[2 * q], rv.x);
            fma2(yb, S2[2 * q + 1], rv.y);
        }

        float* sn = &sh[nxt][0];
#pragma unroll
        for (int q = 0; q < 6; q++) sn[q * 64 + tid] = pf[q];
        __syncthreads();

        const ulonglong2* ap = (const ulonglong2*)(&sh[nxt][4 * 64 + jb]);
        ull za = 0ull, zb = 0ull;
#pragma unroll
        for (int q = 0; q < 4; q++) {
            ulonglong2 av = ap[q];
            fma2(za, S2[2 * q], av.x);
            fma2(zb, S2[2 * q + 1], av.y);
        }

        float yv = (lo2(ya) + hi2(ya)) + (lo2(yb) + hi2(yb));
        float sv = (lo2(za) + hi2(za)) + (lo2(zb) + hi2(zb));
        yv += __shfl_xor_sync(0xffffffffu, yv, 1);
        sv += __shfl_xor_sync(0xffffffffu, sv, 1);
        yv += __shfl_xor_sync(0xffffffffu, yv, 2);
        sv += __shfl_xor_sync(0xffffffffu, sv, 2);
        sa = sv;
        if (jc == 0)
            y[base + (ll)t * Cc + i] = yv;
    }
}

// ---------------- E2 (writes YG planes) ----------------
__global__ __launch_bounds__(768) void e2_k(
    const float* __restrict__ y,
    const float* __restrict__ rr, const float* __restrict__ kk, const float* __restrict__ vv,
    const float* __restrict__ gg, const float* __restrict__ faaaa,
    const float* __restrict__ lnw, unsigned* __restrict__ ygp)
{
    int bt = blockIdx.x;            // b*2048 + t
    int b = bt >> 11, t = bt & 2047;
    ll base = (ll)bt * Cc;
    int c = threadIdx.x;
    int w = c >> 5, h = c >> 6, j = c & 63, lane = c & 31;
    float yv = y[base + c];
    float rv = rr[base + c], kv = kk[base + c], vV = vv[base + c];
    float s1 = yv * yv;
    float s2 = rv * kv * faaaa[h * 64 + j];
#pragma unroll
    for (int o = 16; o; o >>= 1) {
        s1 += __shfl_xor_sync(0xffffffffu, s1, o);
        s2 += __shfl_xor_sync(0xffffffffu, s2, o);
    }
    __shared__ float sh1[24], sh2[24];
    if (lane == 0) { sh1[w] = s1; sh2[w] = s2; }
    __syncthreads();
    float tot = 0.f;
#pragma unroll
    for (int q = 0; q < 24; q++) tot += sh1[q];
    float scale = rsqrtf(tot * (1.f / 768.f) + 1e-5f);
    float rk = sh2[h * 2] + sh2[h * 2 + 1];
    float yo = (yv * scale * lnw[c] + rk * vV) * gg[base + c];
    ygp[(ll)b * 1572864 + (ll)(c >> 1) * 4096 + 2 * t + (c & 1)] = pack_hl(yo);
}

// ---------------- launch ----------------
#define SMEM128 (3 * (2 * 128 * 80 + 16 * 544))
#define SMEM64  (3 * (2 * 64 * 80 + 16 * 544))

extern "C" void kernel_launch(void* const* d_in, const int* in_sizes, int n_in,
                              void* d_out, int out_size)
{
    (void)in_sizes; (void)n_in; (void)out_size;
    const float* x       = (const float*)d_in[0];
    const float* tmaa_r  = (const float*)d_in[2];
    const float* tmaa_w  = (const float*)d_in[3];
    const float* tmaa_k  = (const float*)d_in[4];
    const float* tmaa_v  = (const float*)d_in[5];
    const float* tmaa_a  = (const float*)d_in[6];
    const float* tmaa_g  = (const float*)d_in[7];
    const float* tdecay  = (const float*)d_in[8];
    const float* faaaa   = (const float*)d_in[9];
    const float* taaaaa  = (const float*)d_in[10];
    const float* maa_w1  = (const float*)d_in[11];
    const float* maa_w2  = (const float*)d_in[12];
    const float* dec_w1  = (const float*)d_in[13];
    const float* dec_w2  = (const float*)d_in[14];
    const float* aaa_w1  = (const float*)d_in[15];
    const float* aaa_w2  = (const float*)d_in[16];
    const float* kkk_w1  = (const float*)d_in[17];
    const float* kkk_w2  = (const float*)d_in[18];
    const float* gate_w1 = (const float*)d_in[19];
    const float* gate_w2 = (const float*)d_in[20];
    const float* w_key   = (const float*)d_in[21];
    const float* w_val   = (const float*)d_in[22];
    const float* w_rec   = (const float*)d_in[23];
    const float* w_out   = (const float*)d_in[24];
    const float* lnw     = (const float*)d_in[25];
    float* out = (float*)d_out;

    static int attr_done = 0;
    if (!attr_done) {
        cudaFuncSetAttribute(gemm_k<128>, cudaFuncAttributeMaxDynamicSharedMemorySize, SMEM128);
        cudaFuncSetAttribute(gemm_k<64>,  cudaFuncAttributeMaxDynamicSharedMemorySize, SMEM64);
        attr_done = 1;
    }

    float* ws = 0;
    cudaGetSymbolAddress((void**)&ws, g_ws);

    unsigned* XP   = (unsigned*)(ws + WS_XP);
    unsigned* TMP  = (unsigned*)(ws + WS_TMP);
    unsigned* XBP  = (unsigned*)(ws + WS_XBP);
    unsigned* H1P  = (unsigned*)(ws + WS_H1P);
    unsigned* TM2P = (unsigned*)(ws + WS_TM2P);
    float* GT  = ws + WS_GT;
    float* RIN = ws + WS_RIN;
    float* Y   = ws + WS_Y;
    __nv_bfloat16* WPL = (__nv_bfloat16*)(ws + WS_WPL);

    // ---- weight prep (19 segments) ----
    {
        PrepTab pt;
        int i = 0;
        auto seg = [&](const float* s, int d, int M, int K, int sm, int sk) {
            pt.src[i] = s; pt.dst[i] = d; pt.M[i] = M; pt.K[i] = K; pt.sm[i] = sm; pt.sk[i] = sk; i++;
        };
        seg(maa_w1, 0, 384, 768, 768, 1);
        for (int n = 0; n < 6; n++) seg(maa_w2 + n * 49152, 294912 + n * 49152, 768, 64, 1, 768);
        seg(w_rec, 589824, 768, 384, 384, 1);
        seg(w_key, 884736, 768, 384, 384, 1);
        seg(w_val, 1179648, 768, 384, 384, 1);
        seg(dec_w1, 1474560, 64, 768, 768, 1);
        seg(kkk_w1, 1523712, 64, 768, 768, 1);
        seg(aaa_w1, 1572864, 64, 768, 768, 1);
        seg(dec_w2, 1622016, 768, 64, 64, 1);
        seg(kkk_w2, 1671168, 768, 64, 64, 1);
        seg(aaa_w2, 1720320, 768, 64, 64, 1);
        seg(gate_w1, 1769472, 192, 768, 768, 1);
        seg(gate_w2, 1916928, 768, 192, 192, 1);
        seg(w_out, 2064384, 768, 384, 384, 1);
        prep_w<<<dim3(1152, 1, 19), 256>>>(WPL, pt);
    }
    prep_x<<<(Bb * Cc * Tt) / 256, 256>>>(x, XP);

    // G1) TM planes = tanh(maa_w1 @ x): M=384, K=768
    {
        ZMap zm = {};
        for (int b = 0; b < 2; b++) {
            zm.b[b] = (ll)b * 1572864;
            zm.o[b] = (ll)b * 786432;
            zm.epi[b] = EPI_TANH;
        }
        gemm_k<128><<<dim3(32, 3, 2), 256, SMEM128>>>(WPL, WTOT, XP, 0, TMP,
                                                      0, 0, 2048, 768, 1, 0, 0, zm);
    }

    // G2) MIX -> XB planes: z=n*2+b, M=768, K=64
    {
        ZMap zm = {};
        const float* tmaas[6] = {tmaa_r, tmaa_w, tmaa_k, tmaa_v, tmaa_a, tmaa_g};
        for (int n = 0; n < 6; n++)
            for (int b = 0; b < 2; b++) {
                int z = n * 2 + b;
                zm.a[z]  = 294912 + (ll)n * 49152;
                zm.b[z]  = (ll)b * 786432 + (ll)n * 131072;
                zm.o[z]  = ((ll)n * 2 + b) * 1572864;
                zm.x1[z] = (ll)(tmaas[n] - tmaa_r);
                zm.x2[z] = (ll)b * CTll;
                zm.epi[z] = EPI_MIX;
            }
        gemm_k<128><<<dim3(32, 6, 12), 256, SMEM128>>>(WPL, WTOT, TMP, 0, XBP,
                                                       0, 0, 2048, 64, 1, tmaa_r, x, zm);
    }

    // G3) convs (r,k,v) -> RIN fp32 (B,T,C): z=q*4+g*2+b, M=384, K=384
    {
        ZMap zm = {};
        const int xbi[3] = {0, 2, 3};
        const int rio[3] = {0, 2, 3};
        for (int q = 0; q < 3; q++)
            for (int g = 0; g < 2; g++)
                for (int b = 0; b < 2; b++) {
                    int z = q * 4 + g * 2 + b;
                    zm.a[z] = 589824 + (ll)q * 294912 + (ll)g * 147456;
                    zm.b[z] = ((ll)xbi[q] * 2 + b) * 1572864 + (ll)g * 786432;
                    zm.o[z] = (ll)rio[q] * BTCll + (ll)b * CTll + g * 384;
                    zm.epi[z] = EPI_NONE;
                }
        gemm_k<128><<<dim3(32, 3, 12), 256, SMEM128>>>(WPL, WTOT, XBP, RIN, 0,
                                                       1, Cc, 2048, 384, 0, 0, 0, zm);
    }

    // G4) lora stage1 -> H1 planes: z=q*2+b, M=64, K=768
    {
        ZMap zm = {};
        const int sl[3] = {1, 2, 4};
        for (int q = 0; q < 3; q++)
            for (int b = 0; b < 2; b++) {
                int z = q * 2 + b;
                zm.a[z] = 1474560 + (ll)q * 49152;
                zm.b[z] = ((ll)sl[q] * 2 + b) * 1572864;
                zm.o[z] = ((ll)q * 2 + b) * 131072;
                zm.epi[z] = EPI_TANH;
            }
        gemm_k<64><<<dim3(32, 1, 6), 256, SMEM64>>>(WPL, WTOT, XBP, 0, H1P,
                                                    0, 0, 2048, 768, 1, 0, 0, zm);
    }

    // G5) gate stage1 -> TM2 planes: M=192, K=768
    {
        ZMap zm = {};
        for (int b = 0; b < 2; b++) {
            zm.a[b] = 1769472;
            zm.b[b] = (10LL + b) * 1572864;
            zm.o[b] = (ll)b * 393216;
            zm.epi[b] = EPI_TANH;
        }
        gemm_k<64><<<dim3(32, 3, 2), 256, SMEM64>>>(WPL, WTOT, XBP, 0, TM2P,
                                                    0, 0, 2048, 768, 1, 0, 0, zm);
    }

    // G6) lora stage2 -> fp32 (wdec, KL, AS): z=q*2+b, M=768, K=64
    {
        ZMap zm = {};
        ll od[3] = {WS_RIN + BTCll, WS_KL, WS_AS};
        const int ep[3] = {EPI_DECAY, EPI_NONE, EPI_SIG};
        ll xd[3] = {0, 0, (ll)(taaaaa - tdecay)};
        for (int q = 0; q < 3; q++)
            for (int b = 0; b < 2; b++) {
                int z = q * 2 + b;
                zm.a[z]  = 1622016 + (ll)q * 49152;
                zm.b[z]  = ((ll)q * 2 + b) * 131072;
                zm.o[z]  = od[q] + (ll)b * CTll;
                zm.x1[z] = xd[q];
                zm.epi[z] = ep[q];
            }
        gemm_k<128><<<dim3(32, 6, 6), 256, SMEM128>>>(WPL, WTOT, H1P, ws, 0,
                                                      1, Cc, 2048, 64, 0, tdecay, 0, zm);
    }

    // G7) gate stage2 -> GT fp32: M=768, K=192
    {
        ZMap zm = {};
        for (int b = 0; b < 2; b++) {
            zm.a[b] = 1916928;
            zm.b[b] = (ll)b * 393216;
            zm.o[b] = (ll)b * CTll;
            zm.epi[b] = EPI_NONE;
        }
        gemm_k<128><<<dim3(32, 6, 2), 256, SMEM128>>>(WPL, WTOT, TM2P, GT, 0,
                                                      1, Cc, 2048, 192, 0, 0, 0, zm);
    }

    // E1
    e1_k<<<(Bb * Tt * Hh) / 8, 256>>>(RIN + 2 * BTCll, ws + WS_KL, ws + WS_AS,
                                      RIN + 4 * BTCll, RIN + 5 * BTCll);

    // WKV7
    wkv7_k<<<Bb * Hh * RS, 64>>>(RIN, Y);

    // E2 -> YG planes (reuse XP)
    e2_k<<<Bb * Tt, 768>>>(Y, RIN, RIN + 2 * BTCll, RIN + 3 * BTCll,
                           GT, faaaa, lnw, XP);

    // G11) output conv: z=g*2+b, M=384, K=384, out fp32 (B,C,T)
    {
        ZMap zm = {};
        for (int g = 0; g < 2; g++)
            for (int b = 0; b < 2; b++) {
                int z = g * 2 + b;
                zm.a[z] = 2064384 + (ll)g * 147456;
                zm.b[z] = (ll)b * 1572864 + (ll)g * 786432;
                zm.o[z] = (ll)b * CTll + (ll)g * 384 * Tt;
                zm.epi[z] = EPI_NONE;
            }
        gemm_k<128><<<dim3(32, 3, 4), 256, SMEM128>>>(WPL, WTOT, XP, out, 0,
                                                      Tt, 1, 2048, 384, 0, 0, 0, zm);
    }
}